// round 1
// baseline (speedup 1.0000x reference)
#include <cuda_runtime.h>
#include <cstdint>

#define FULL 0xffffffffu
#define N_OPS_C 20
#define N_QUBITS_C 8

struct OpList { int op[N_OPS_C]; };  // packed: kind | (w0<<2) | (w1<<5); kind 0=rx 1=ry 2=rz 3=cnot

// ---------------------------------------------------------------------------
// Device helpers. All register arrays indexed only with compile-time constants
// (loops fully unrolled); runtime masks handled via shuffles or 3-way selects.
// ---------------------------------------------------------------------------

__device__ __forceinline__ float sel3(const float (&a)[8], int j, int m) {
    // m in {1,2,4}; j is a compile-time constant at each call site
    float v1 = a[j ^ 1], v2 = a[j ^ 2], v4 = a[j ^ 4];
    return (m == 1) ? v1 : (m == 2) ? v2 : v4;
}

__device__ __forceinline__ void exchg(const float (&re)[8], const float (&im)[8],
                                      float (&pr)[8], float (&pi)[8], int bit) {
    if (bit >= 3) {
        int m = 1 << (bit - 3);
#pragma unroll
        for (int j = 0; j < 8; j++) {
            pr[j] = __shfl_xor_sync(FULL, re[j], m);
            pi[j] = __shfl_xor_sync(FULL, im[j], m);
        }
    } else {
        int m = 1 << bit;
#pragma unroll
        for (int j = 0; j < 8; j++) {
            pr[j] = sel3(re, j, m);
            pi[j] = sel3(im, j, m);
        }
    }
}

// RX: n = c*mine - i*s*partner (same formula for both halves of the pair)
__device__ __forceinline__ void gate_rx(float (&re)[8], float (&im)[8],
                                        int bit, float c, float s, int lane) {
    float pr[8], pi[8];
    exchg(re, im, pr, pi, bit);
#pragma unroll
    for (int j = 0; j < 8; j++) {
        float r = re[j], i = im[j];
        re[j] = c * r + s * pi[j];
        im[j] = c * i - s * pr[j];
    }
}

// RY: n = c*mine + (bit? +s : -s)*partner  (real matrix)
__device__ __forceinline__ void gate_ry(float (&re)[8], float (&im)[8],
                                        int bit, float c, float s, int lane) {
    float pr[8], pi[8];
    exchg(re, im, pr, pi, bit);
#pragma unroll
    for (int j = 0; j < 8; j++) {
        int g = (lane << 3) | j;
        float ss = ((g >> bit) & 1) ? s : -s;
        re[j] = c * re[j] + ss * pr[j];
        im[j] = c * im[j] + ss * pi[j];
    }
}

// RZ: amp *= (c + i*ss), ss = bit? s : -s. Diagonal — no exchange.
__device__ __forceinline__ void gate_rz(float (&re)[8], float (&im)[8],
                                        int bit, float c, float s, int lane) {
#pragma unroll
    for (int j = 0; j < 8; j++) {
        int g = (lane << 3) | j;
        float ss = ((g >> bit) & 1) ? s : -s;
        float r = re[j], i = im[j];
        re[j] = c * r - ss * i;
        im[j] = c * i + ss * r;
    }
}

// Generic complex 2x2: u = {u00r,u00i,u01r,u01i,u10r,u10i,u11r,u11i}
__device__ __forceinline__ void gate_u(float (&re)[8], float (&im)[8],
                                       int bit, const float* __restrict__ u, int lane) {
    float pr[8], pi[8];
    exchg(re, im, pr, pi, bit);
    float u0 = u[0], u1 = u[1], u2 = u[2], u3 = u[3];
    float u4 = u[4], u5 = u[5], u6 = u[6], u7 = u[7];
#pragma unroll
    for (int j = 0; j < 8; j++) {
        int g = (lane << 3) | j;
        bool hi = (g >> bit) & 1;
        float dr = hi ? u6 : u0, di = hi ? u7 : u1;
        float orr = hi ? u4 : u2, oi = hi ? u5 : u3;
        float r = re[j], i = im[j], qr = pr[j], qi = pi[j];
        re[j] = dr * r - di * i + orr * qr - oi * qi;
        im[j] = dr * i + di * r + orr * qi + oi * qr;
    }
}

__device__ __forceinline__ void gate_cnot(float (&re)[8], float (&im)[8],
                                          int cb, int tb, int lane) {
    if (tb >= 3) {
        int m = 1 << (tb - 3);
#pragma unroll
        for (int j = 0; j < 8; j++) {
            float qr = __shfl_xor_sync(FULL, re[j], m);
            float qi = __shfl_xor_sync(FULL, im[j], m);
            int g = (lane << 3) | j;
            if ((g >> cb) & 1) { re[j] = qr; im[j] = qi; }
        }
    } else {
        int m = 1 << tb;
        float tr[8], ti[8];
#pragma unroll
        for (int j = 0; j < 8; j++) { tr[j] = re[j]; ti[j] = im[j]; }
#pragma unroll
        for (int j = 0; j < 8; j++) {
            int g = (lane << 3) | j;
            if ((g >> cb) & 1) { re[j] = sel3(tr, j, m); im[j] = sel3(ti, j, m); }
        }
    }
}

// ---------------------------------------------------------------------------
// Main kernel: one warp per batch item. 8 complex amplitudes per lane.
// Index bits: [7:3] = lane, [2:0] = in-thread j. Wire w <-> bit (7-w).
// ---------------------------------------------------------------------------
__global__ __launch_bounds__(256)
void qcnn_kernel(const float* __restrict__ x,
                 const float* __restrict__ rl,
                 const float* __restrict__ trx,
                 const float* __restrict__ tryy,
                 float* __restrict__ out,
                 OpList ops, int bsz) {
    __shared__ float s_cs[N_OPS_C][2];  // (c,s) per RL op (rotations only)
    __shared__ float s_uf[8];           // fused RY(ty)*RX(tx) matrix

    int tid = threadIdx.x;
    if (tid < N_OPS_C) {
        float c, s;
        sincosf(rl[tid] * 0.5f, &s, &c);
        s_cs[tid][0] = c; s_cs[tid][1] = s;
    } else if (tid == N_OPS_C) {
        float cx, sx, cy, sy;
        sincosf(trx[0] * 0.5f, &sx, &cx);
        sincosf(tryy[0] * 0.5f, &sy, &cy);
        // U = Ry * Rx
        s_uf[0] = cy * cx;  s_uf[1] = sy * sx;   // u00
        s_uf[2] = -sy * cx; s_uf[3] = -cy * sx;  // u01
        s_uf[4] = sy * cx;  s_uf[5] = -cy * sx;  // u10
        s_uf[6] = cy * cx;  s_uf[7] = -sy * sx;  // u11
    }
    __syncthreads();

    int warp = blockIdx.x * (blockDim.x >> 5) + (tid >> 5);
    int lane = tid & 31;
    if (warp >= bsz) return;
    int b = warp;

    // ---- Initial 8 RY gates on |0...0> collapse to a product state ----
    float myc, mys;
    float ang = (lane < 8) ? x[b * 8 + lane] * 0.5f : 0.0f;
    sincosf(ang, &mys, &myc);
    float cw[8], sw[8];
#pragma unroll
    for (int i = 0; i < 8; i++) {
        cw[i] = __shfl_sync(FULL, myc, i);
        sw[i] = __shfl_sync(FULL, mys, i);
    }
    float F = 1.0f;
#pragma unroll
    for (int w = 0; w < 5; w++)  // wires 0..4 are lane bits 4..0
        F *= ((lane >> (4 - w)) & 1) ? sw[w] : cw[w];

    float re[8], im[8];
#pragma unroll
    for (int j = 0; j < 8; j++) {
        float f = F;
        f *= ((j >> 2) & 1) ? sw[5] : cw[5];   // wire 5 = bit 2
        f *= ((j >> 1) & 1) ? sw[6] : cw[6];   // wire 6 = bit 1
        f *= (j & 1) ? sw[7] : cw[7];          // wire 7 = bit 0
        re[j] = f; im[j] = 0.0f;
    }

    // ---- 20 RL ops ----
    for (int k = 0; k < N_OPS_C; k++) {
        int o = ops.op[k];
        int kd = o & 3;
        int wa = (o >> 2) & 7;
        if (kd == 3) {
            int wb = (o >> 5) & 7;
            gate_cnot(re, im, 7 - wa, 7 - wb, lane);
        } else {
            float c = s_cs[k][0], s = s_cs[k][1];
            int bit = 7 - wa;
            if (kd == 0)      gate_rx(re, im, bit, c, s, lane);
            else if (kd == 1) gate_ry(re, im, bit, c, s, lane);
            else              gate_rz(re, im, bit, c, s, lane);
        }
    }

    // ---- Final layer: fused RX(tx)+RY(ty) on each wire ----
    for (int w = 0; w < 8; w++)
        gate_u(re, im, 7 - w, s_uf, lane);

    // ---- Readout: <Z_q> = sum_i p_i * (1 - 2*bit_{7-q}(i)) ----
    float p[8];
#pragma unroll
    for (int j = 0; j < 8; j++) p[j] = re[j] * re[j] + im[j] * im[j];
    float S = 0.f, A0 = 0.f, A1 = 0.f, A2 = 0.f;
#pragma unroll
    for (int j = 0; j < 8; j++) {
        S += p[j];
        A0 += (j & 1) ? -p[j] : p[j];
        A1 += ((j >> 1) & 1) ? -p[j] : p[j];
        A2 += ((j >> 2) & 1) ? -p[j] : p[j];
    }
    float z[8];
#pragma unroll
    for (int q = 0; q < 5; q++)        // wires 0..4: sign from lane bit (4-q)
        z[q] = ((lane >> (4 - q)) & 1) ? -S : S;
    z[5] = A2; z[6] = A1; z[7] = A0;   // wires 5..7: local bits 2,1,0

#pragma unroll
    for (int off = 16; off; off >>= 1) {
#pragma unroll
        for (int q = 0; q < 8; q++)
            z[q] += __shfl_xor_sync(FULL, z[q], off);
    }
    if (lane == 0) {
        float4* o4 = reinterpret_cast<float4*>(out + (size_t)b * 8);
        o4[0] = make_float4(z[0], z[1], z[2], z[3]);
        o4[1] = make_float4(z[4], z[5], z[6], z[7]);
    }
}

// ---------------------------------------------------------------------------
// Host: exact reproduction of np.random.RandomState(0) draws for _RL_OPS.
//  - randint(n): one 32-bit draw & mask, masked rejection (legacy 32-bit path)
//  - choice(8,2,replace=False): permutation(8)[:2], Fisher-Yates with
//    random_interval (masked rejection), i = 7..1
// Recomputed on every call (deterministic, no caching, no CUDA API use).
// ---------------------------------------------------------------------------
namespace {
struct MT19937 {
    uint32_t mt[624]; int mti;
    void seed(uint32_t s) {
        mt[0] = s;
        for (int i = 1; i < 624; i++)
            mt[i] = 1812433253u * (mt[i - 1] ^ (mt[i - 1] >> 30)) + (uint32_t)i;
        mti = 624;
    }
    uint32_t next() {
        if (mti >= 624) {
            for (int i = 0; i < 624; i++) {
                uint32_t y = (mt[i] & 0x80000000u) | (mt[(i + 1) % 624] & 0x7fffffffu);
                mt[i] = mt[(i + 397) % 624] ^ (y >> 1) ^ ((y & 1u) ? 0x9908b0dfu : 0u);
            }
            mti = 0;
        }
        uint32_t y = mt[mti++];
        y ^= y >> 11;
        y ^= (y << 7) & 0x9d2c5680u;
        y ^= (y << 15) & 0xefc60000u;
        y ^= y >> 18;
        return y;
    }
    // random_interval: uniform in [0, max], masked rejection on 32-bit draws
    uint32_t interval(uint32_t max) {
        if (max == 0) return 0;
        uint32_t mask = max;
        mask |= mask >> 1; mask |= mask >> 2; mask |= mask >> 4;
        mask |= mask >> 8; mask |= mask >> 16;
        uint32_t v;
        do { v = next() & mask; } while (v > max);
        return v;
    }
};

OpList build_ops() {
    MT19937 rng;
    rng.seed(0);
    OpList ol;
    for (int k = 0; k < N_OPS_C; k++) {
        int kd = (int)(rng.next() & 3u);  // randint(4): rng=3, mask=3, no rejection
        int w0, w1;
        if (kd == 3) {  // cnot: choice(8,2,replace=False) = permutation(8)[:2]
            int perm[8];
            for (int i = 0; i < 8; i++) perm[i] = i;
            for (int i = 7; i > 0; i--) {
                uint32_t j = rng.interval((uint32_t)i);
                int t = perm[i]; perm[i] = perm[j]; perm[j] = t;
            }
            w0 = perm[0]; w1 = perm[1];
        } else {
            w0 = (int)(rng.next() & 7u);  // randint(8): rng=7, mask=7, no rejection
            w1 = 0;
        }
        ol.op[k] = kd | (w0 << 2) | (w1 << 5);
    }
    return ol;
}
}  // namespace

extern "C" void kernel_launch(void* const* d_in, const int* in_sizes, int n_in,
                              void* d_out, int out_size) {
    const float* x    = (const float*)d_in[0];  // [BSZ, 8] f32
    const float* rl   = (const float*)d_in[1];  // [20] f32
    const float* trx  = (const float*)d_in[2];  // [1] f32
    const float* tryy = (const float*)d_in[3];  // [1] f32
    float* out = (float*)d_out;                 // [BSZ, 8] f32

    int bsz = in_sizes[0] / N_QUBITS_C;
    OpList ops = build_ops();

    int warps_per_block = 8;
    dim3 block(warps_per_block * 32);
    dim3 grid((bsz + warps_per_block - 1) / warps_per_block);
    qcnn_kernel<<<grid, block>>>(x, rl, trx, tryy, out, ops, bsz);
}

// round 3
// speedup vs baseline: 2.0323x; 2.0323x over previous
#include <cuda_runtime.h>
#include <cstdint>

#define FULL 0xffffffffu
#define N_OPS_C 20
#define N_QUBITS_C 8

// ===========================================================================
// Compile-time reproduction of np.random.RandomState(0) draws for _RL_OPS.
// (Identical logic to the runtime version that passed in R1 — now constexpr,
// so the whole gate sequence specializes at compile time.)
// ===========================================================================
struct OpsArr { int op[N_OPS_C]; };  // kind | (w0<<2) | (w1<<5); 0=rx 1=ry 2=rz 3=cnot

struct CxRng {
    uint32_t mt[624]; int mti;
    constexpr CxRng() : mt{}, mti(624) {
        mt[0] = 0u;
        for (int i = 1; i < 624; i++)
            mt[i] = 1812433253u * (mt[i - 1] ^ (mt[i - 1] >> 30)) + (uint32_t)i;
    }
    constexpr uint32_t next() {
        if (mti >= 624) {
            for (int i = 0; i < 624; i++) {
                uint32_t y = (mt[i] & 0x80000000u) | (mt[(i + 1) % 624] & 0x7fffffffu);
                mt[i] = mt[(i + 397) % 624] ^ (y >> 1) ^ ((y & 1u) ? 0x9908b0dfu : 0u);
            }
            mti = 0;
        }
        uint32_t y = mt[mti++];
        y ^= y >> 11;
        y ^= (y << 7) & 0x9d2c5680u;
        y ^= (y << 15) & 0xefc60000u;
        y ^= y >> 18;
        return y;
    }
    constexpr uint32_t interval(uint32_t mx) {
        if (mx == 0u) return 0u;
        uint32_t mask = mx;
        mask |= mask >> 1; mask |= mask >> 2; mask |= mask >> 4;
        mask |= mask >> 8; mask |= mask >> 16;
        uint32_t v = next() & mask;
        while (v > mx) v = next() & mask;
        return v;
    }
};

constexpr OpsArr build_ops_cx() {
    CxRng rng{};
    OpsArr ol{};
    for (int k = 0; k < N_OPS_C; k++) {
        int kd = (int)(rng.next() & 3u);   // randint(4)
        int w0 = 0, w1 = 0;
        if (kd == 3) {                     // choice(8,2,replace=False) = permutation(8)[:2]
            int perm[8] = {0, 1, 2, 3, 4, 5, 6, 7};
            for (int i = 7; i > 0; i--) {
                uint32_t j = rng.interval((uint32_t)i);
                int t = perm[i]; perm[i] = perm[(int)j]; perm[(int)j] = t;
            }
            w0 = perm[0]; w1 = perm[1];
        } else {
            w0 = (int)(rng.next() & 7u);   // randint(8)
        }
        ol.op[k] = kd | (w0 << 2) | (w1 << 5);
    }
    return ol;
}

constexpr OpsArr OPS = build_ops_cx();

// ===========================================================================
// Gates templated on bit position. Index bits: [7:3]=lane, [2:0]=in-thread j.
// Wire w <-> bit (7-w). BIT>=3: lane exchange via shfl, per-gate sign select.
// BIT<3: everything compile-time -> pure FFMA pair updates.
// ===========================================================================

template<int BIT>
__device__ __forceinline__ void rx_g(float (&re)[8], float (&im)[8],
                                     float c, float s, int lane) {
    if constexpr (BIT >= 3) {
        constexpr int m = 1 << (BIT - 3);
#pragma unroll
        for (int j = 0; j < 8; j++) {
            float pr = __shfl_xor_sync(FULL, re[j], m);
            float pi = __shfl_xor_sync(FULL, im[j], m);
            float r = re[j], i = im[j];
            re[j] = c * r + s * pi;
            im[j] = c * i - s * pr;
        }
    } else {
        constexpr int m = 1 << BIT;
#pragma unroll
        for (int j0 = 0; j0 < 8; j0++) {
            if ((j0 & m) == 0) {
                const int j1 = j0 | m;
                float r0 = re[j0], i0 = im[j0], r1 = re[j1], i1 = im[j1];
                re[j0] = c * r0 + s * i1;  im[j0] = c * i0 - s * r1;
                re[j1] = c * r1 + s * i0;  im[j1] = c * i1 - s * r0;
            }
        }
    }
}

template<int BIT>
__device__ __forceinline__ void ry_g(float (&re)[8], float (&im)[8],
                                     float c, float s, int lane) {
    if constexpr (BIT >= 3) {
        constexpr int m = 1 << (BIT - 3);
        float ss = ((lane >> (BIT - 3)) & 1) ? s : -s;   // once per gate
#pragma unroll
        for (int j = 0; j < 8; j++) {
            float pr = __shfl_xor_sync(FULL, re[j], m);
            float pi = __shfl_xor_sync(FULL, im[j], m);
            re[j] = c * re[j] + ss * pr;
            im[j] = c * im[j] + ss * pi;
        }
    } else {
        constexpr int m = 1 << BIT;
#pragma unroll
        for (int j0 = 0; j0 < 8; j0++) {
            if ((j0 & m) == 0) {
                const int j1 = j0 | m;
                float r0 = re[j0], i0 = im[j0], r1 = re[j1], i1 = im[j1];
                re[j0] = c * r0 - s * r1;  re[j1] = s * r0 + c * r1;
                im[j0] = c * i0 - s * i1;  im[j1] = s * i0 + c * i1;
            }
        }
    }
}

template<int BIT>
__device__ __forceinline__ void rz_g(float (&re)[8], float (&im)[8],
                                     float c, float s, int lane) {
    if constexpr (BIT >= 3) {
        float ss = ((lane >> (BIT - 3)) & 1) ? s : -s;   // once per gate
#pragma unroll
        for (int j = 0; j < 8; j++) {
            float r = re[j], i = im[j];
            re[j] = c * r - ss * i;
            im[j] = c * i + ss * r;
        }
    } else {
        constexpr int m = 1 << BIT;
#pragma unroll
        for (int j = 0; j < 8; j++) {
            float r = re[j], i = im[j];
            if (j & m) { re[j] = c * r - s * i;  im[j] = c * i + s * r; }
            else       { re[j] = c * r + s * i;  im[j] = c * i - s * r; }
        }
    }
}

template<int CB, int TB>
__device__ __forceinline__ void cnot_g(float (&re)[8], float (&im)[8], int lane) {
    if constexpr (CB >= 3 && TB >= 3) {
        constexpr int mt = 1 << (TB - 3);
        bool ctl = (lane >> (CB - 3)) & 1;
#pragma unroll
        for (int j = 0; j < 8; j++) {
            float qr = __shfl_xor_sync(FULL, re[j], mt);
            float qi = __shfl_xor_sync(FULL, im[j], mt);
            if (ctl) { re[j] = qr; im[j] = qi; }
        }
    } else if constexpr (CB >= 3 && TB < 3) {
        constexpr int mt = 1 << TB;
        bool ctl = (lane >> (CB - 3)) & 1;
#pragma unroll
        for (int j0 = 0; j0 < 8; j0++) {
            if ((j0 & mt) == 0) {
                const int j1 = j0 | mt;
                float r0 = re[j0], i0 = im[j0];
                re[j0] = ctl ? re[j1] : r0;   im[j0] = ctl ? im[j1] : i0;
                re[j1] = ctl ? r0 : re[j1];   im[j1] = ctl ? i0 : im[j1];
            }
        }
    } else if constexpr (CB < 3 && TB >= 3) {
        constexpr int mc = 1 << CB;
        constexpr int mt = 1 << (TB - 3);
#pragma unroll
        for (int j = 0; j < 8; j++) {
            if (j & mc) {                    // compile-time: only controlled j's
                re[j] = __shfl_xor_sync(FULL, re[j], mt);
                im[j] = __shfl_xor_sync(FULL, im[j], mt);
            }
        }
    } else {                                 // both local: pure register permutation
        constexpr int mc = 1 << CB;
        constexpr int mt = 1 << TB;
#pragma unroll
        for (int j0 = 0; j0 < 8; j0++) {
            if ((j0 & mc) && !(j0 & mt)) {
                const int j1 = j0 | mt;
                float tr = re[j0], ti = im[j0];
                re[j0] = re[j1]; im[j0] = im[j1];
                re[j1] = tr;     im[j1] = ti;
            }
        }
    }
}

// Fused U = Ry(ty)*Rx(tx) = [[ar+i*ai, br+i*bi], [-br+i*bi, ar-i*ai]]
template<int BIT>
__device__ __forceinline__ void u_g(float (&re)[8], float (&im)[8],
                                    float ar, float ai, float br, float bi, int lane) {
    if constexpr (BIT >= 3) {
        constexpr int m = 1 << (BIT - 3);
        bool hi = (lane >> (BIT - 3)) & 1;
        float di  = hi ? -ai : ai;           // once per gate
        float orr = hi ? -br : br;
#pragma unroll
        for (int j = 0; j < 8; j++) {
            float qr = __shfl_xor_sync(FULL, re[j], m);
            float qi = __shfl_xor_sync(FULL, im[j], m);
            float r = re[j], i = im[j];
            re[j] = ar * r - di * i + orr * qr - bi * qi;
            im[j] = ar * i + di * r + orr * qi + bi * qr;
        }
    } else {
        constexpr int m = 1 << BIT;
#pragma unroll
        for (int j0 = 0; j0 < 8; j0++) {
            if ((j0 & m) == 0) {
                const int j1 = j0 | m;
                float r0 = re[j0], i0 = im[j0], r1 = re[j1], i1 = im[j1];
                re[j0] =  ar * r0 - ai * i0 + br * r1 - bi * i1;
                im[j0] =  ar * i0 + ai * r0 + br * i1 + bi * r1;
                re[j1] = -br * r0 - bi * i0 + ar * r1 + ai * i1;
                im[j1] = -br * i0 + bi * r0 + ar * i1 - ai * r1;
            }
        }
    }
}

// ---- Compile-time unrolled RL op sequence ----
template<int K>
__device__ __forceinline__ void rl_ops(float (&re)[8], float (&im)[8],
                                       const float (*cs)[2], int lane) {
    if constexpr (K < N_OPS_C) {
        constexpr int o  = OPS.op[K];
        constexpr int kd = o & 3;
        if constexpr (kd == 3) {
            cnot_g<7 - ((o >> 2) & 7), 7 - ((o >> 5) & 7)>(re, im, lane);
        } else {
            float c = cs[K][0], s = cs[K][1];
            constexpr int bit = 7 - ((o >> 2) & 7);
            if constexpr (kd == 0)      rx_g<bit>(re, im, c, s, lane);
            else if constexpr (kd == 1) ry_g<bit>(re, im, c, s, lane);
            else                        rz_g<bit>(re, im, c, s, lane);
        }
        rl_ops<K + 1>(re, im, cs, lane);
    }
}

template<int W>
__device__ __forceinline__ void final_layer(float (&re)[8], float (&im)[8],
                                            float ar, float ai, float br, float bi,
                                            int lane) {
    if constexpr (W < N_QUBITS_C) {
        u_g<7 - W>(re, im, ar, ai, br, bi, lane);
        final_layer<W + 1>(re, im, ar, ai, br, bi, lane);
    }
}

// ===========================================================================
// Main kernel: one warp per batch item, 8 complex amps per lane.
// ===========================================================================
__global__ __launch_bounds__(256)
void qcnn_kernel(const float* __restrict__ x,
                 const float* __restrict__ rl,
                 const float* __restrict__ trx,
                 const float* __restrict__ tryy,
                 float* __restrict__ out, int bsz) {
    __shared__ float s_cs[N_OPS_C][2];
    __shared__ float s_uf[4];   // ar, ai, br, bi

    int tid = threadIdx.x;
    if (tid < N_OPS_C) {
        float c, s;
        sincosf(rl[tid] * 0.5f, &s, &c);
        s_cs[tid][0] = c; s_cs[tid][1] = s;
    } else if (tid == N_OPS_C) {
        float cx, sx, cy, sy;
        sincosf(trx[0] * 0.5f, &sx, &cx);
        sincosf(tryy[0] * 0.5f, &sy, &cy);
        s_uf[0] = cy * cx;   // ar
        s_uf[1] = sy * sx;   // ai
        s_uf[2] = -sy * cx;  // br
        s_uf[3] = -cy * sx;  // bi
    }
    __syncthreads();

    int warp = blockIdx.x * (blockDim.x >> 5) + (tid >> 5);
    int lane = tid & 31;
    if (warp >= bsz) return;
    int b = warp;

    // ---- Initial 8 RY gates on |0...0> = product state ----
    float myc, mys;
    float ang = (lane < 8) ? __ldg(x + b * 8 + lane) * 0.5f : 0.0f;
    sincosf(ang, &mys, &myc);
    float cw[8], sw[8];
#pragma unroll
    for (int i = 0; i < 8; i++) {
        cw[i] = __shfl_sync(FULL, myc, i);
        sw[i] = __shfl_sync(FULL, mys, i);
    }
    float F = 1.0f;
#pragma unroll
    for (int w = 0; w < 5; w++)
        F *= ((lane >> (4 - w)) & 1) ? sw[w] : cw[w];

    float re[8], im[8];
#pragma unroll
    for (int j = 0; j < 8; j++) {
        float f = F;
        f *= ((j >> 2) & 1) ? sw[5] : cw[5];
        f *= ((j >> 1) & 1) ? sw[6] : cw[6];
        f *= (j & 1) ? sw[7] : cw[7];
        re[j] = f; im[j] = 0.0f;
    }

    // ---- 20 RL ops (fully specialized at compile time) ----
    rl_ops<0>(re, im, s_cs, lane);

    // ---- Final fused RX+RY layer on all 8 wires ----
    {
        float ar = s_uf[0], ai = s_uf[1], br = s_uf[2], bi = s_uf[3];
        final_layer<0>(re, im, ar, ai, br, bi, lane);
    }

    // ---- Readout: <Z_q> ----
    float p[8];
#pragma unroll
    for (int j = 0; j < 8; j++) p[j] = re[j] * re[j] + im[j] * im[j];
    float S = 0.f, A0 = 0.f, A1 = 0.f, A2 = 0.f;
#pragma unroll
    for (int j = 0; j < 8; j++) {
        S += p[j];
        A0 += (j & 1) ? -p[j] : p[j];
        A1 += ((j >> 1) & 1) ? -p[j] : p[j];
        A2 += ((j >> 2) & 1) ? -p[j] : p[j];
    }
    float z[8];
#pragma unroll
    for (int q = 0; q < 5; q++)
        z[q] = ((lane >> (4 - q)) & 1) ? -S : S;
    z[5] = A2; z[6] = A1; z[7] = A0;

#pragma unroll
    for (int off = 16; off; off >>= 1) {
#pragma unroll
        for (int q = 0; q < 8; q++)
            z[q] += __shfl_xor_sync(FULL, z[q], off);
    }
    if (lane == 0) {
        float4* o4 = reinterpret_cast<float4*>(out + (size_t)b * 8);
        o4[0] = make_float4(z[0], z[1], z[2], z[3]);
        o4[1] = make_float4(z[4], z[5], z[6], z[7]);
    }
}

extern "C" void kernel_launch(void* const* d_in, const int* in_sizes, int n_in,
                              void* d_out, int out_size) {
    const float* x    = (const float*)d_in[0];
    const float* rl   = (const float*)d_in[1];
    const float* trx  = (const float*)d_in[2];
    const float* tryy = (const float*)d_in[3];
    float* out = (float*)d_out;

    int bsz = in_sizes[0] / N_QUBITS_C;

    int warps_per_block = 8;
    dim3 block(warps_per_block * 32);
    dim3 grid((bsz + warps_per_block - 1) / warps_per_block);
    qcnn_kernel<<<grid, block>>>(x, rl, trx, tryy, out, bsz);
}

// round 4
// speedup vs baseline: 2.1362x; 1.0511x over previous
#include <cuda_runtime.h>
#include <cstdint>

#define FULL 0xffffffffu
#define N_OPS_C 20
#define N_QUBITS_C 8

using u64 = unsigned long long;

// ===========================================================================
// Compile-time reproduction of np.random.RandomState(0) draws for _RL_OPS
// (validated: R1/R3 kernels built on this passed with rel_err ~2e-7).
// ===========================================================================
struct OpsArr { int op[N_OPS_C]; };  // kind | (w0<<2) | (w1<<5); 0=rx 1=ry 2=rz 3=cnot

struct CxRng {
    uint32_t mt[624]; int mti;
    constexpr CxRng() : mt{}, mti(624) {
        mt[0] = 0u;
        for (int i = 1; i < 624; i++)
            mt[i] = 1812433253u * (mt[i - 1] ^ (mt[i - 1] >> 30)) + (uint32_t)i;
    }
    constexpr uint32_t next() {
        if (mti >= 624) {
            for (int i = 0; i < 624; i++) {
                uint32_t y = (mt[i] & 0x80000000u) | (mt[(i + 1) % 624] & 0x7fffffffu);
                mt[i] = mt[(i + 397) % 624] ^ (y >> 1) ^ ((y & 1u) ? 0x9908b0dfu : 0u);
            }
            mti = 0;
        }
        uint32_t y = mt[mti++];
        y ^= y >> 11;
        y ^= (y << 7) & 0x9d2c5680u;
        y ^= (y << 15) & 0xefc60000u;
        y ^= y >> 18;
        return y;
    }
    constexpr uint32_t interval(uint32_t mx) {
        if (mx == 0u) return 0u;
        uint32_t mask = mx;
        mask |= mask >> 1; mask |= mask >> 2; mask |= mask >> 4;
        mask |= mask >> 8; mask |= mask >> 16;
        uint32_t v = next() & mask;
        while (v > mx) v = next() & mask;
        return v;
    }
};

constexpr OpsArr build_ops_cx() {
    CxRng rng{};
    OpsArr ol{};
    for (int k = 0; k < N_OPS_C; k++) {
        int kd = (int)(rng.next() & 3u);   // randint(4)
        int w0 = 0, w1 = 0;
        if (kd == 3) {                     // choice(8,2,replace=False) = permutation(8)[:2]
            int perm[8] = {0, 1, 2, 3, 4, 5, 6, 7};
            for (int i = 7; i > 0; i--) {
                uint32_t j = rng.interval((uint32_t)i);
                int t = perm[i]; perm[i] = perm[(int)j]; perm[(int)j] = t;
            }
            w0 = perm[0]; w1 = perm[1];
        } else {
            w0 = (int)(rng.next() & 7u);   // randint(8)
        }
        ol.op[k] = kd | (w0 << 2) | (w1 << 5);
    }
    return ol;
}

constexpr OpsArr OPS = build_ops_cx();

// ===========================================================================
// Packed f32x2 primitives (Blackwell: FFMA2 via PTX only)
// Amplitude = u64 packed (re = lo, im = hi).
// ===========================================================================
__device__ __forceinline__ u64 pk2(float lo, float hi) {
    u64 r; asm("mov.b64 %0, {%1, %2};" : "=l"(r) : "f"(lo), "f"(hi)); return r;
}
__device__ __forceinline__ void upk2(u64 v, float& lo, float& hi) {
    asm("mov.b64 {%0, %1}, %2;" : "=f"(lo), "=f"(hi) : "l"(v));
}
__device__ __forceinline__ u64 sw2(u64 v) {   // (a,b) -> (b,a)
    u64 r;
    asm("{\n\t.reg .b32 a, b;\n\tmov.b64 {a, b}, %1;\n\tmov.b64 %0, {b, a};\n\t}"
        : "=l"(r) : "l"(v));
    return r;
}
__device__ __forceinline__ u64 fma2(u64 a, u64 b, u64 c) {
    u64 d; asm("fma.rn.f32x2 %0, %1, %2, %3;" : "=l"(d) : "l"(a), "l"(b), "l"(c)); return d;
}
__device__ __forceinline__ u64 mul2(u64 a, u64 b) {
    u64 d; asm("mul.rn.f32x2 %0, %1, %2;" : "=l"(d) : "l"(a), "l"(b)); return d;
}
// Shuffle a packed amp from lane^m: returns normal pack (pr,pi)
__device__ __forceinline__ u64 shfl_pk(u64 v, int m) {
    float lo, hi; upk2(v, lo, hi);
    float plo = __shfl_xor_sync(FULL, lo, m);
    float phi = __shfl_xor_sync(FULL, hi, m);
    return pk2(plo, phi);
}
// Shuffle with swapped pack: returns (pi,pr) — swap comes free at pack time
__device__ __forceinline__ u64 shfl_pk_sw(u64 v, int m) {
    float lo, hi; upk2(v, lo, hi);
    float plo = __shfl_xor_sync(FULL, lo, m);
    float phi = __shfl_xor_sync(FULL, hi, m);
    return pk2(phi, plo);
}
// Both packs from one pair of shuffles
__device__ __forceinline__ void shfl_pk_both(u64 v, int m, u64& q, u64& qsw) {
    float lo, hi; upk2(v, lo, hi);
    float plo = __shfl_xor_sync(FULL, lo, m);
    float phi = __shfl_xor_sync(FULL, hi, m);
    q = pk2(plo, phi); qsw = pk2(phi, plo);
}

// ===========================================================================
// Gates. Index bits: [7:3]=lane, [2:0]=in-thread j. Wire w <-> bit (7-w).
// Coefficient packs: CC=(c,c) SS=(s,s) SN=(-s,-s) SPN=(s,-s) NSP=(-s,s)
// ===========================================================================

// RX: re' = c*r + s*pi ; im' = c*i - s*pr  ->  v' = CC*v + SPN (.) swap(partner)
template<int BIT>
__device__ __forceinline__ void rx_g(u64 (&v)[8], u64 CC, u64 SPN, int lane) {
    if constexpr (BIT >= 3) {
        constexpr int m = 1 << (BIT - 3);
#pragma unroll
        for (int j = 0; j < 8; j++) {
            u64 psw = shfl_pk_sw(v[j], m);
            v[j] = fma2(SPN, psw, mul2(CC, v[j]));
        }
    } else {
        constexpr int m = 1 << BIT;
#pragma unroll
        for (int j0 = 0; j0 < 8; j0++) {
            if ((j0 & m) == 0) {
                const int j1 = j0 | m;
                u64 sw0 = sw2(v[j0]), sw1 = sw2(v[j1]);
                v[j0] = fma2(SPN, sw1, mul2(CC, v[j0]));
                v[j1] = fma2(SPN, sw0, mul2(CC, v[j1]));
            }
        }
    }
}

// RY: real matrix -> v0' = CC*v0 + SN*v1 ; v1' = CC*v1 + SS*v0
template<int BIT>
__device__ __forceinline__ void ry_g(u64 (&v)[8], u64 CC, u64 SS, u64 SN, int lane) {
    if constexpr (BIT >= 3) {
        constexpr int m = 1 << (BIT - 3);
        u64 ssP = ((lane >> (BIT - 3)) & 1) ? SS : SN;   // once per gate
#pragma unroll
        for (int j = 0; j < 8; j++) {
            u64 p = shfl_pk(v[j], m);
            v[j] = fma2(ssP, p, mul2(CC, v[j]));
        }
    } else {
        constexpr int m = 1 << BIT;
#pragma unroll
        for (int j0 = 0; j0 < 8; j0++) {
            if ((j0 & m) == 0) {
                const int j1 = j0 | m;
                u64 v0 = v[j0], v1 = v[j1];
                v[j0] = fma2(SN, v1, mul2(CC, v0));
                v[j1] = fma2(SS, v0, mul2(CC, v1));
            }
        }
    }
}

// RZ diagonal: bit set: (c+is)  -> v' = CC*v + NSP (.) swap(v)
//              bit clear: (c-is)-> v' = CC*v + SPN (.) swap(v)
template<int BIT>
__device__ __forceinline__ void rz_g(u64 (&v)[8], u64 CC, u64 SPN, u64 NSP, int lane) {
    if constexpr (BIT >= 3) {
        u64 zc = ((lane >> (BIT - 3)) & 1) ? NSP : SPN;  // once per gate
#pragma unroll
        for (int j = 0; j < 8; j++)
            v[j] = fma2(zc, sw2(v[j]), mul2(CC, v[j]));
    } else {
        constexpr int m = 1 << BIT;
#pragma unroll
        for (int j = 0; j < 8; j++) {
            u64 zc = (j & m) ? NSP : SPN;                // compile-time pick
            v[j] = fma2(zc, sw2(v[j]), mul2(CC, v[j]));
        }
    }
}

template<int CB, int TB>
__device__ __forceinline__ void cnot_g(u64 (&v)[8], int lane) {
    if constexpr (CB >= 3 && TB >= 3) {
        constexpr int mt = 1 << (TB - 3);
        bool ctl = (lane >> (CB - 3)) & 1;
#pragma unroll
        for (int j = 0; j < 8; j++) {
            u64 q = shfl_pk(v[j], mt);
            if (ctl) v[j] = q;
        }
    } else if constexpr (CB >= 3 && TB < 3) {
        constexpr int mt = 1 << TB;
        bool ctl = (lane >> (CB - 3)) & 1;
#pragma unroll
        for (int j0 = 0; j0 < 8; j0++) {
            if ((j0 & mt) == 0) {
                const int j1 = j0 | mt;
                u64 a = v[j0], b = v[j1];
                v[j0] = ctl ? b : a;
                v[j1] = ctl ? a : b;
            }
        }
    } else if constexpr (CB < 3 && TB >= 3) {
        constexpr int mc = 1 << CB;
        constexpr int mt = 1 << (TB - 3);
#pragma unroll
        for (int j = 0; j < 8; j++) {
            if (j & mc)                      // compile-time: only controlled j's
                v[j] = shfl_pk(v[j], mt);
        }
    } else {
        constexpr int mc = 1 << CB;
        constexpr int mt = 1 << TB;
#pragma unroll
        for (int j0 = 0; j0 < 8; j0++) {
            if ((j0 & mc) && !(j0 & mt)) {
                const int j1 = j0 | mt;
                u64 t = v[j0]; v[j0] = v[j1]; v[j1] = t;
            }
        }
    }
}

// Fused U = Ry(ty)*Rx(tx) = [[ar+i*ai, br+i*bi], [-br+i*bi, ar-i*ai]]
// Packs: AR2=(ar,ar) AIP=(-ai,ai) AIN=(ai,-ai) BR2=(br,br) BRN2=(-br,-br) BIP=(-bi,bi)
template<int BIT>
__device__ __forceinline__ void u_g(u64 (&v)[8],
                                    u64 AR2, u64 AIP, u64 AIN,
                                    u64 BR2, u64 BRN2, u64 BIP, int lane) {
    if constexpr (BIT >= 3) {
        constexpr int m = 1 << (BIT - 3);
        bool hi = (lane >> (BIT - 3)) & 1;
        u64 DIP = hi ? AIN : AIP;    // (-di, di), di = hi? -ai : ai
        u64 OR2 = hi ? BRN2 : BR2;   // (orr, orr), orr = hi? -br : br
#pragma unroll
        for (int j = 0; j < 8; j++) {
            u64 q, qsw;
            shfl_pk_both(v[j], m, q, qsw);
            u64 vsw = sw2(v[j]);
            v[j] = fma2(AR2, v[j], fma2(DIP, vsw, fma2(OR2, q, mul2(BIP, qsw))));
        }
    } else {
        constexpr int m = 1 << BIT;
#pragma unroll
        for (int j0 = 0; j0 < 8; j0++) {
            if ((j0 & m) == 0) {
                const int j1 = j0 | m;
                u64 v0 = v[j0], v1 = v[j1];
                u64 sw0 = sw2(v0), sw1 = sw2(v1);
                v[j0] = fma2(AR2, v0, fma2(AIP, sw0, fma2(BR2,  v1, mul2(BIP, sw1))));
                v[j1] = fma2(BRN2, v0, fma2(BIP, sw0, fma2(AR2, v1, mul2(AIN, sw1))));
            }
        }
    }
}

// ---- Compile-time unrolled RL op sequence ----
template<int K>
__device__ __forceinline__ void rl_ops(u64 (&v)[8], const u64* __restrict__ pk, int lane) {
    if constexpr (K < N_OPS_C) {
        constexpr int o  = OPS.op[K];
        constexpr int kd = o & 3;
        if constexpr (kd == 3) {
            cnot_g<7 - ((o >> 2) & 7), 7 - ((o >> 5) & 7)>(v, lane);
        } else {
            const u64* g = pk + K * 5;   // [0]=(c,c) [1]=(s,s) [2]=(-s,-s) [3]=(s,-s) [4]=(-s,s)
            constexpr int bit = 7 - ((o >> 2) & 7);
            if constexpr (kd == 0)      rx_g<bit>(v, g[0], g[3], lane);
            else if constexpr (kd == 1) ry_g<bit>(v, g[0], g[1], g[2], lane);
            else                        rz_g<bit>(v, g[0], g[3], g[4], lane);
        }
        rl_ops<K + 1>(v, pk, lane);
    }
}

template<int W>
__device__ __forceinline__ void final_layer(u64 (&v)[8],
                                            u64 AR2, u64 AIP, u64 AIN,
                                            u64 BR2, u64 BRN2, u64 BIP, int lane) {
    if constexpr (W < N_QUBITS_C) {
        u_g<7 - W>(v, AR2, AIP, AIN, BR2, BRN2, BIP, lane);
        final_layer<W + 1>(v, AR2, AIP, AIN, BR2, BRN2, BIP, lane);
    }
}

// ===========================================================================
// Main kernel: one warp per batch item, 8 packed complex amps per lane.
// ===========================================================================
__global__ __launch_bounds__(256)
void qcnn_kernel(const float* __restrict__ x,
                 const float* __restrict__ rl,
                 const float* __restrict__ trx,
                 const float* __restrict__ tryy,
                 float* __restrict__ out, int bsz) {
    __shared__ u64 s_pk[N_OPS_C * 5];
    __shared__ u64 s_up[6];

    int tid = threadIdx.x;
    if (tid < N_OPS_C) {
        float c, s;
        sincosf(rl[tid] * 0.5f, &s, &c);
        u64* g = s_pk + tid * 5;
        g[0] = pk2(c, c);  g[1] = pk2(s, s);   g[2] = pk2(-s, -s);
        g[3] = pk2(s, -s); g[4] = pk2(-s, s);
    } else if (tid == N_OPS_C) {
        float cx, sx, cy, sy;
        sincosf(trx[0] * 0.5f, &sx, &cx);
        sincosf(tryy[0] * 0.5f, &sy, &cy);
        float ar = cy * cx, ai = sy * sx, br = -sy * cx, bi = -cy * sx;
        s_up[0] = pk2(ar, ar);   s_up[1] = pk2(-ai, ai);  s_up[2] = pk2(ai, -ai);
        s_up[3] = pk2(br, br);   s_up[4] = pk2(-br, -br); s_up[5] = pk2(-bi, bi);
    }
    __syncthreads();

    int warp = blockIdx.x * (blockDim.x >> 5) + (tid >> 5);
    int lane = tid & 31;
    if (warp >= bsz) return;
    int b = warp;

    // ---- Initial 8 RY gates on |0...0> = product state ----
    float myc, mys;
    float ang = (lane < 8) ? __ldg(x + b * 8 + lane) * 0.5f : 0.0f;
    sincosf(ang, &mys, &myc);
    float cw[8], sw[8];
#pragma unroll
    for (int i = 0; i < 8; i++) {
        cw[i] = __shfl_sync(FULL, myc, i);
        sw[i] = __shfl_sync(FULL, mys, i);
    }
    float F = 1.0f;
#pragma unroll
    for (int w = 0; w < 5; w++)
        F *= ((lane >> (4 - w)) & 1) ? sw[w] : cw[w];

    u64 v[8];
#pragma unroll
    for (int j = 0; j < 8; j++) {
        float f = F;
        f *= ((j >> 2) & 1) ? sw[5] : cw[5];
        f *= ((j >> 1) & 1) ? sw[6] : cw[6];
        f *= (j & 1) ? sw[7] : cw[7];
        v[j] = pk2(f, 0.0f);
    }

    // ---- 20 RL ops (fully specialized, packed f32x2 math) ----
    rl_ops<0>(v, s_pk, lane);

    // ---- Final fused RX+RY layer on all 8 wires ----
    {
        u64 AR2 = s_up[0], AIP = s_up[1], AIN = s_up[2];
        u64 BR2 = s_up[3], BRN2 = s_up[4], BIP = s_up[5];
        final_layer<0>(v, AR2, AIP, AIN, BR2, BRN2, BIP, lane);
    }

    // ---- Readout ----
    // Per-thread partial sums: S (all +), A0/A1/A2 (sign by local bit 0/1/2)
    float S = 0.f, A0 = 0.f, A1 = 0.f, A2 = 0.f;
#pragma unroll
    for (int j = 0; j < 8; j++) {
        float r, i; upk2(v[j], r, i);
        float pj = fmaf(r, r, i * i);
        S  += pj;
        A0 += (j & 1)        ? -pj : pj;
        A1 += ((j >> 1) & 1) ? -pj : pj;
        A2 += ((j >> 2) & 1) ? -pj : pj;
    }
    // Cross-lane: FWHT on S (5 signed butterfly rounds -> lane 2^k holds the
    // single-bit-signed sum), plain butterfly sums for A0..A2.
#pragma unroll
    for (int off = 16; off; off >>= 1) {
        float pS = __shfl_xor_sync(FULL, S,  off);
        float p0 = __shfl_xor_sync(FULL, A0, off);
        float p1 = __shfl_xor_sync(FULL, A1, off);
        float p2 = __shfl_xor_sync(FULL, A2, off);
        S  = (lane & off) ? (pS - S) : (S + pS);
        A0 += p0; A1 += p1; A2 += p2;
    }
    // z[q] (q<5) = H(S) at lane 2^(4-q);  z[5..7] = sums of A2,A1,A0 (any lane)
    if (lane && (lane & (lane - 1)) == 0 && lane <= 16)
        out[(size_t)b * 8 + (5 - __ffs(lane))] = S;
    if (lane == 0) {
        float* o = out + (size_t)b * 8;
        o[5] = A2; o[6] = A1; o[7] = A0;
    }
}

extern "C" void kernel_launch(void* const* d_in, const int* in_sizes, int n_in,
                              void* d_out, int out_size) {
    const float* x    = (const float*)d_in[0];
    const float* rl   = (const float*)d_in[1];
    const float* trx  = (const float*)d_in[2];
    const float* tryy = (const float*)d_in[3];
    float* out = (float*)d_out;

    int bsz = in_sizes[0] / N_QUBITS_C;

    int warps_per_block = 8;
    dim3 block(warps_per_block * 32);
    dim3 grid((bsz + warps_per_block - 1) / warps_per_block);
    qcnn_kernel<<<grid, block>>>(x, rl, trx, tryy, out, bsz);
}

// round 5
// speedup vs baseline: 2.4561x; 1.1498x over previous
#include <cuda_runtime.h>
#include <cstdint>

#define FULL 0xffffffffu
#define N_OPS_C 20
#define N_QUBITS_C 8

using u64 = unsigned long long;

// ===========================================================================
// Compile-time reproduction of np.random.RandomState(0) draws for _RL_OPS
// (validated: R1/R3/R4 kernels built on this passed with rel_err ~2e-7).
// ===========================================================================
struct OpsArr { int op[N_OPS_C]; };  // kind | (w0<<2) | (w1<<5); 0=rx 1=ry 2=rz 3=cnot

struct CxRng {
    uint32_t mt[624]; int mti;
    constexpr CxRng() : mt{}, mti(624) {
        mt[0] = 0u;
        for (int i = 1; i < 624; i++)
            mt[i] = 1812433253u * (mt[i - 1] ^ (mt[i - 1] >> 30)) + (uint32_t)i;
    }
    constexpr uint32_t next() {
        if (mti >= 624) {
            for (int i = 0; i < 624; i++) {
                uint32_t y = (mt[i] & 0x80000000u) | (mt[(i + 1) % 624] & 0x7fffffffu);
                mt[i] = mt[(i + 397) % 624] ^ (y >> 1) ^ ((y & 1u) ? 0x9908b0dfu : 0u);
            }
            mti = 0;
        }
        uint32_t y = mt[mti++];
        y ^= y >> 11;
        y ^= (y << 7) & 0x9d2c5680u;
        y ^= (y << 15) & 0xefc60000u;
        y ^= y >> 18;
        return y;
    }
    constexpr uint32_t interval(uint32_t mx) {
        if (mx == 0u) return 0u;
        uint32_t mask = mx;
        mask |= mask >> 1; mask |= mask >> 2; mask |= mask >> 4;
        mask |= mask >> 8; mask |= mask >> 16;
        uint32_t v = next() & mask;
        while (v > mx) v = next() & mask;
        return v;
    }
};

constexpr OpsArr build_ops_cx() {
    CxRng rng{};
    OpsArr ol{};
    for (int k = 0; k < N_OPS_C; k++) {
        int kd = (int)(rng.next() & 3u);   // randint(4)
        int w0 = 0, w1 = 0;
        if (kd == 3) {                     // choice(8,2,replace=False) = permutation(8)[:2]
            int perm[8] = {0, 1, 2, 3, 4, 5, 6, 7};
            for (int i = 7; i > 0; i--) {
                uint32_t j = rng.interval((uint32_t)i);
                int t = perm[i]; perm[i] = perm[(int)j]; perm[(int)j] = t;
            }
            w0 = perm[0]; w1 = perm[1];
        } else {
            w0 = (int)(rng.next() & 7u);   // randint(8)
        }
        ol.op[k] = kd | (w0 << 2) | (w1 << 5);
    }
    return ol;
}

constexpr OpsArr OPS = build_ops_cx();

// ===========================================================================
// Packed f32x2 primitives. Amplitude = u64 packed (re = lo, im = hi).
// ===========================================================================
__device__ __forceinline__ u64 pk2(float lo, float hi) {
    u64 r; asm("mov.b64 %0, {%1, %2};" : "=l"(r) : "f"(lo), "f"(hi)); return r;
}
__device__ __forceinline__ void upk2(u64 v, float& lo, float& hi) {
    asm("mov.b64 {%0, %1}, %2;" : "=f"(lo), "=f"(hi) : "l"(v));
}
__device__ __forceinline__ u64 sw2(u64 v) {   // (a,b) -> (b,a)
    u64 r;
    asm("{\n\t.reg .b32 a, b;\n\tmov.b64 {a, b}, %1;\n\tmov.b64 %0, {b, a};\n\t}"
        : "=l"(r) : "l"(v));
    return r;
}
__device__ __forceinline__ u64 fma2(u64 a, u64 b, u64 c) {
    u64 d; asm("fma.rn.f32x2 %0, %1, %2, %3;" : "=l"(d) : "l"(a), "l"(b), "l"(c)); return d;
}
__device__ __forceinline__ u64 mul2(u64 a, u64 b) {
    u64 d; asm("mul.rn.f32x2 %0, %1, %2;" : "=l"(d) : "l"(a), "l"(b)); return d;
}
__device__ __forceinline__ u64 shfl_pk(u64 v, int m) {
    float lo, hi; upk2(v, lo, hi);
    float plo = __shfl_xor_sync(FULL, lo, m);
    float phi = __shfl_xor_sync(FULL, hi, m);
    return pk2(plo, phi);
}
__device__ __forceinline__ u64 shfl_pk_sw(u64 v, int m) {   // returns (pi,pr)
    float lo, hi; upk2(v, lo, hi);
    float plo = __shfl_xor_sync(FULL, lo, m);
    float phi = __shfl_xor_sync(FULL, hi, m);
    return pk2(phi, plo);
}
__device__ __forceinline__ void shfl_pk_both(u64 v, int m, u64& q, u64& qsw) {
    float lo, hi; upk2(v, lo, hi);
    float plo = __shfl_xor_sync(FULL, lo, m);
    float phi = __shfl_xor_sync(FULL, hi, m);
    q = pk2(plo, phi); qsw = pk2(phi, plo);
}

// ===========================================================================
// Layout: 2 items per warp, 16 lanes per item (group bit = lane bit 4).
// Amplitude index bits: [7:4] = sublane t (lane bits 3..0), [3:0] = local j.
// Wire w <-> bit (7-w). BIT>=4: lane gate (xor mask < 16 stays in group).
// Coefficient packs: CC=(c,c) SS=(s,s) SN=(-s,-s) SPN=(s,-s) NSP=(-s,s)
// ===========================================================================

template<int BIT>
__device__ __forceinline__ void rx_g(u64 (&v)[16], u64 CC, u64 SPN, int lane) {
    if constexpr (BIT >= 4) {
        constexpr int m = 1 << (BIT - 4);
#pragma unroll
        for (int j = 0; j < 16; j++) {
            u64 psw = shfl_pk_sw(v[j], m);
            v[j] = fma2(SPN, psw, mul2(CC, v[j]));
        }
    } else {
        constexpr int m = 1 << BIT;
#pragma unroll
        for (int j0 = 0; j0 < 16; j0++) {
            if ((j0 & m) == 0) {
                const int j1 = j0 | m;
                u64 sw0 = sw2(v[j0]), sw1 = sw2(v[j1]);
                v[j0] = fma2(SPN, sw1, mul2(CC, v[j0]));
                v[j1] = fma2(SPN, sw0, mul2(CC, v[j1]));
            }
        }
    }
}

template<int BIT>
__device__ __forceinline__ void ry_g(u64 (&v)[16], u64 CC, u64 SS, u64 SN, int lane) {
    if constexpr (BIT >= 4) {
        constexpr int m = 1 << (BIT - 4);
        u64 ssP = ((lane >> (BIT - 4)) & 1) ? SS : SN;   // once per gate
#pragma unroll
        for (int j = 0; j < 16; j++) {
            u64 p = shfl_pk(v[j], m);
            v[j] = fma2(ssP, p, mul2(CC, v[j]));
        }
    } else {
        constexpr int m = 1 << BIT;
#pragma unroll
        for (int j0 = 0; j0 < 16; j0++) {
            if ((j0 & m) == 0) {
                const int j1 = j0 | m;
                u64 v0 = v[j0], v1 = v[j1];
                v[j0] = fma2(SN, v1, mul2(CC, v0));
                v[j1] = fma2(SS, v0, mul2(CC, v1));
            }
        }
    }
}

template<int BIT>
__device__ __forceinline__ void rz_g(u64 (&v)[16], u64 CC, u64 SPN, u64 NSP, int lane) {
    if constexpr (BIT >= 4) {
        u64 zc = ((lane >> (BIT - 4)) & 1) ? NSP : SPN;  // once per gate
#pragma unroll
        for (int j = 0; j < 16; j++)
            v[j] = fma2(zc, sw2(v[j]), mul2(CC, v[j]));
    } else {
        constexpr int m = 1 << BIT;
#pragma unroll
        for (int j = 0; j < 16; j++) {
            u64 zc = (j & m) ? NSP : SPN;                // compile-time pick
            v[j] = fma2(zc, sw2(v[j]), mul2(CC, v[j]));
        }
    }
}

template<int CB, int TB>
__device__ __forceinline__ void cnot_g(u64 (&v)[16], int lane) {
    if constexpr (CB >= 4 && TB >= 4) {
        constexpr int mt = 1 << (TB - 4);
        bool ctl = (lane >> (CB - 4)) & 1;
#pragma unroll
        for (int j = 0; j < 16; j++) {
            u64 q = shfl_pk(v[j], mt);
            if (ctl) v[j] = q;
        }
    } else if constexpr (CB >= 4 && TB < 4) {
        constexpr int mt = 1 << TB;
        bool ctl = (lane >> (CB - 4)) & 1;
#pragma unroll
        for (int j0 = 0; j0 < 16; j0++) {
            if ((j0 & mt) == 0) {
                const int j1 = j0 | mt;
                u64 a = v[j0], b = v[j1];
                v[j0] = ctl ? b : a;
                v[j1] = ctl ? a : b;
            }
        }
    } else if constexpr (CB < 4 && TB >= 4) {
        constexpr int mc = 1 << CB;
        constexpr int mt = 1 << (TB - 4);
#pragma unroll
        for (int j = 0; j < 16; j++) {
            if (j & mc)                      // compile-time: only controlled j's
                v[j] = shfl_pk(v[j], mt);
        }
    } else {
        constexpr int mc = 1 << CB;
        constexpr int mt = 1 << TB;
#pragma unroll
        for (int j0 = 0; j0 < 16; j0++) {
            if ((j0 & mc) && !(j0 & mt)) {
                const int j1 = j0 | mt;
                u64 t = v[j0]; v[j0] = v[j1]; v[j1] = t;
            }
        }
    }
}

// Fused U = Ry(ty)*Rx(tx) = [[ar+i*ai, br+i*bi], [-br+i*bi, ar-i*ai]]
template<int BIT>
__device__ __forceinline__ void u_g(u64 (&v)[16],
                                    u64 AR2, u64 AIP, u64 AIN,
                                    u64 BR2, u64 BRN2, u64 BIP, int lane) {
    if constexpr (BIT >= 4) {
        constexpr int m = 1 << (BIT - 4);
        bool hi = (lane >> (BIT - 4)) & 1;
        u64 DIP = hi ? AIN : AIP;
        u64 OR2 = hi ? BRN2 : BR2;
#pragma unroll
        for (int j = 0; j < 16; j++) {
            u64 q, qsw;
            shfl_pk_both(v[j], m, q, qsw);
            u64 vsw = sw2(v[j]);
            v[j] = fma2(AR2, v[j], fma2(DIP, vsw, fma2(OR2, q, mul2(BIP, qsw))));
        }
    } else {
        constexpr int m = 1 << BIT;
#pragma unroll
        for (int j0 = 0; j0 < 16; j0++) {
            if ((j0 & m) == 0) {
                const int j1 = j0 | m;
                u64 v0 = v[j0], v1 = v[j1];
                u64 sw0 = sw2(v0), sw1 = sw2(v1);
                v[j0] = fma2(AR2, v0, fma2(AIP, sw0, fma2(BR2,  v1, mul2(BIP, sw1))));
                v[j1] = fma2(BRN2, v0, fma2(BIP, sw0, fma2(AR2, v1, mul2(AIN, sw1))));
            }
        }
    }
}

// ---- Compile-time unrolled RL op sequence ----
template<int K>
__device__ __forceinline__ void rl_ops(u64 (&v)[16], const u64* __restrict__ pk, int lane) {
    if constexpr (K < N_OPS_C) {
        constexpr int o  = OPS.op[K];
        constexpr int kd = o & 3;
        if constexpr (kd == 3) {
            cnot_g<7 - ((o >> 2) & 7), 7 - ((o >> 5) & 7)>(v, lane);
        } else {
            const u64* g = pk + K * 5;   // [0]=(c,c) [1]=(s,s) [2]=(-s,-s) [3]=(s,-s) [4]=(-s,s)
            constexpr int bit = 7 - ((o >> 2) & 7);
            if constexpr (kd == 0)      rx_g<bit>(v, g[0], g[3], lane);
            else if constexpr (kd == 1) ry_g<bit>(v, g[0], g[1], g[2], lane);
            else                        rz_g<bit>(v, g[0], g[3], g[4], lane);
        }
        rl_ops<K + 1>(v, pk, lane);
    }
}

template<int W>
__device__ __forceinline__ void final_layer(u64 (&v)[16],
                                            u64 AR2, u64 AIP, u64 AIN,
                                            u64 BR2, u64 BRN2, u64 BIP, int lane) {
    if constexpr (W < N_QUBITS_C) {
        u_g<7 - W>(v, AR2, AIP, AIN, BR2, BRN2, BIP, lane);
        final_layer<W + 1>(v, AR2, AIP, AIN, BR2, BRN2, BIP, lane);
    }
}

// ===========================================================================
// Main kernel: one warp per TWO batch items, 16 packed amps per lane.
// ===========================================================================
__global__ __launch_bounds__(256)
void qcnn_kernel(const float* __restrict__ x,
                 const float* __restrict__ rl,
                 const float* __restrict__ trx,
                 const float* __restrict__ tryy,
                 float* __restrict__ out, int bsz) {
    __shared__ u64 s_pk[N_OPS_C * 5];
    __shared__ u64 s_up[6];

    int tid = threadIdx.x;
    if (tid < N_OPS_C) {
        float c, s;
        sincosf(rl[tid] * 0.5f, &s, &c);
        u64* g = s_pk + tid * 5;
        g[0] = pk2(c, c);  g[1] = pk2(s, s);   g[2] = pk2(-s, -s);
        g[3] = pk2(s, -s); g[4] = pk2(-s, s);
    } else if (tid == N_OPS_C) {
        float cx, sx, cy, sy;
        sincosf(trx[0] * 0.5f, &sx, &cx);
        sincosf(tryy[0] * 0.5f, &sy, &cy);
        float ar = cy * cx, ai = sy * sx, br = -sy * cx, bi = -cy * sx;
        s_up[0] = pk2(ar, ar);   s_up[1] = pk2(-ai, ai);  s_up[2] = pk2(ai, -ai);
        s_up[3] = pk2(br, br);   s_up[4] = pk2(-br, -br); s_up[5] = pk2(-bi, bi);
    }
    __syncthreads();

    int warp = blockIdx.x * (blockDim.x >> 5) + (tid >> 5);
    int lane = tid & 31;
    int t = lane & 15;                       // sublane within item group
    long b = (long)warp * 2 + (lane >> 4);   // item index
    if (b >= bsz) return;

    // ---- Initial 8 RY gates on |0...0> = product state ----
    float myc, mys;
    float ang = (t < 8) ? __ldg(x + b * 8 + t) * 0.5f : 0.0f;
    sincosf(ang, &mys, &myc);
    float cw[8], sw[8];
#pragma unroll
    for (int w = 0; w < 8; w++) {
        int src = (lane & 16) | w;           // broadcast within own 16-lane group
        cw[w] = __shfl_sync(FULL, myc, src);
        sw[w] = __shfl_sync(FULL, mys, src);
    }
    // Wires 0..3 <-> bits 7..4 = t bits 3..0
    float F = 1.0f;
#pragma unroll
    for (int w = 0; w < 4; w++)
        F *= ((t >> (3 - w)) & 1) ? sw[w] : cw[w];

    u64 v[16];
#pragma unroll
    for (int j = 0; j < 16; j++) {
        float f = F;
        // Wires 4..7 <-> bits 3..0 = j bits 3..0
        f *= ((j >> 3) & 1) ? sw[4] : cw[4];
        f *= ((j >> 2) & 1) ? sw[5] : cw[5];
        f *= ((j >> 1) & 1) ? sw[6] : cw[6];
        f *= (j & 1) ? sw[7] : cw[7];
        v[j] = pk2(f, 0.0f);
    }

    // ---- 20 RL ops (fully specialized, packed f32x2 math) ----
    rl_ops<0>(v, s_pk, lane);

    // ---- Final fused RX+RY layer on all 8 wires ----
    {
        u64 AR2 = s_up[0], AIP = s_up[1], AIN = s_up[2];
        u64 BR2 = s_up[3], BRN2 = s_up[4], BIP = s_up[5];
        final_layer<0>(v, AR2, AIP, AIN, BR2, BRN2, BIP, lane);
    }

    // ---- Readout ----
    // Per-thread sums: S (all +), A3..A0 (sign by local bit 3..0 = wires 4..7)
    float S = 0.f, A0 = 0.f, A1 = 0.f, A2 = 0.f, A3 = 0.f;
#pragma unroll
    for (int j = 0; j < 16; j++) {
        float r, i; upk2(v[j], r, i);
        float pj = fmaf(r, r, i * i);
        S  += pj;
        A0 += (j & 1)        ? -pj : pj;
        A1 += ((j >> 1) & 1) ? -pj : pj;
        A2 += ((j >> 2) & 1) ? -pj : pj;
        A3 += ((j >> 3) & 1) ? -pj : pj;
    }
    // Cross-lane within 16-lane group: FWHT on S (4 signed rounds), plain sums
    // for A0..A3. Masks 8,4,2,1 never cross the group boundary (bit 4).
#pragma unroll
    for (int off = 8; off; off >>= 1) {
        float pS = __shfl_xor_sync(FULL, S,  off);
        float p0 = __shfl_xor_sync(FULL, A0, off);
        float p1 = __shfl_xor_sync(FULL, A1, off);
        float p2 = __shfl_xor_sync(FULL, A2, off);
        float p3 = __shfl_xor_sync(FULL, A3, off);
        S  = (lane & off) ? (pS - S) : (S + pS);
        A0 += p0; A1 += p1; A2 += p2; A3 += p3;
    }
    // z[q], q<4: FWHT value at t = 1<<(3-q)  ->  q = 4 - ffs(t)
    // z[4..7] = A3, A2, A1, A0 (written by t == 0)
    float* o = out + (size_t)b * 8;
    if (t && !(t & (t - 1)))
        o[4 - __ffs(t)] = S;
    if (t == 0) {
        o[4] = A3; o[5] = A2; o[6] = A1; o[7] = A0;
    }
}

extern "C" void kernel_launch(void* const* d_in, const int* in_sizes, int n_in,
                              void* d_out, int out_size) {
    const float* x    = (const float*)d_in[0];
    const float* rl   = (const float*)d_in[1];
    const float* trx  = (const float*)d_in[2];
    const float* tryy = (const float*)d_in[3];
    float* out = (float*)d_out;

    int bsz = in_sizes[0] / N_QUBITS_C;

    int warps_per_block = 8;
    int items_per_block = warps_per_block * 2;
    dim3 block(warps_per_block * 32);
    dim3 grid((bsz + items_per_block - 1) / items_per_block);
    qcnn_kernel<<<grid, block>>>(x, rl, trx, tryy, out, bsz);
}

// round 6
// speedup vs baseline: 2.9335x; 1.1944x over previous
#include <cuda_runtime.h>
#include <cstdint>

#define FULL 0xffffffffu
#define N_OPS_C 20
#define N_QUBITS_C 8

using u64 = unsigned long long;

// ===========================================================================
// Compile-time reproduction of np.random.RandomState(0) draws for _RL_OPS
// (validated across R1/R3/R4/R5: rel_err ~2e-7).
// ===========================================================================
struct OpsArr { int op[N_OPS_C]; };  // kind | (w0<<2) | (w1<<5); 0=rx 1=ry 2=rz 3=cnot

struct CxRng {
    uint32_t mt[624]; int mti;
    constexpr CxRng() : mt{}, mti(624) {
        mt[0] = 0u;
        for (int i = 1; i < 624; i++)
            mt[i] = 1812433253u * (mt[i - 1] ^ (mt[i - 1] >> 30)) + (uint32_t)i;
    }
    constexpr uint32_t next() {
        if (mti >= 624) {
            for (int i = 0; i < 624; i++) {
                uint32_t y = (mt[i] & 0x80000000u) | (mt[(i + 1) % 624] & 0x7fffffffu);
                mt[i] = mt[(i + 397) % 624] ^ (y >> 1) ^ ((y & 1u) ? 0x9908b0dfu : 0u);
            }
            mti = 0;
        }
        uint32_t y = mt[mti++];
        y ^= y >> 11;
        y ^= (y << 7) & 0x9d2c5680u;
        y ^= (y << 15) & 0xefc60000u;
        y ^= y >> 18;
        return y;
    }
    constexpr uint32_t interval(uint32_t mx) {
        if (mx == 0u) return 0u;
        uint32_t mask = mx;
        mask |= mask >> 1; mask |= mask >> 2; mask |= mask >> 4;
        mask |= mask >> 8; mask |= mask >> 16;
        uint32_t v = next() & mask;
        while (v > mx) v = next() & mask;
        return v;
    }
};

constexpr OpsArr build_ops_cx() {
    CxRng rng{};
    OpsArr ol{};
    for (int k = 0; k < N_OPS_C; k++) {
        int kd = (int)(rng.next() & 3u);
        int w0 = 0, w1 = 0;
        if (kd == 3) {
            int perm[8] = {0, 1, 2, 3, 4, 5, 6, 7};
            for (int i = 7; i > 0; i--) {
                uint32_t j = rng.interval((uint32_t)i);
                int t = perm[i]; perm[i] = perm[(int)j]; perm[(int)j] = t;
            }
            w0 = perm[0]; w1 = perm[1];
        } else {
            w0 = (int)(rng.next() & 7u);
        }
        ol.op[k] = kd | (w0 << 2) | (w1 << 5);
    }
    return ol;
}

constexpr OpsArr OPS = build_ops_cx();

// ===========================================================================
// Compile-time circuit compiler.
// Emission ops: 0=CNOT(ew=ctl, ew2=tgt), 1=fused SU(2) U (ew=wire, ew2=matrix),
//               2=singleton rotation (ew=wire, ew2=k, ekind=kind).
// Matrices: product of rotations; k>=0 -> angle rl[k], k==-1 -> theta_rx,
//           k==-2 -> theta_ry.
// pre_*: rotations preceding the first CNOT on a wire -> absorbed into init.
// ===========================================================================
struct Plan {
    int n_emit;
    int etype[40], ew[40], ew2[40], ekind[40];
    int n_mat;
    int mlen[24], mk[24][24], mkind[24][24];
    int pre_len[8], pre_k[8][20], pre_kind[8][20];
};

constexpr void plan_flush(Plan& P, int (&plen)[8], int (&pk)[8][20], int (&pkd)[8][20],
                          bool (&seen)[8], int w) {
    if (plen[w] == 0) return;
    if (!seen[w]) {                    // absorb into init
        P.pre_len[w] = plen[w];
        for (int i = 0; i < plen[w]; i++) {
            P.pre_k[w][i] = pk[w][i]; P.pre_kind[w][i] = pkd[w][i];
        }
    } else if (plen[w] == 1) {         // singleton: specialized rotation
        P.etype[P.n_emit] = 2; P.ew[P.n_emit] = w;
        P.ew2[P.n_emit] = pk[w][0]; P.ekind[P.n_emit] = pkd[w][0];
        P.n_emit++;
    } else {                           // fused SU(2)
        int m = P.n_mat++;
        P.mlen[m] = plen[w];
        for (int i = 0; i < plen[w]; i++) {
            P.mk[m][i] = pk[w][i]; P.mkind[m][i] = pkd[w][i];
        }
        P.etype[P.n_emit] = 1; P.ew[P.n_emit] = w; P.ew2[P.n_emit] = m;
        P.n_emit++;
    }
    plen[w] = 0;
}

constexpr Plan build_plan() {
    Plan P{};
    int plen[8] = {}; int pk[8][20] = {}; int pkd[8][20] = {};
    bool seen[8] = {};
    for (int k = 0; k < N_OPS_C; k++) {
        int o = OPS.op[k]; int kd = o & 3;
        int w0 = (o >> 2) & 7; int w1 = (o >> 5) & 7;
        if (kd == 3) {
            plan_flush(P, plen, pk, pkd, seen, w0);
            plan_flush(P, plen, pk, pkd, seen, w1);
            seen[w0] = true; seen[w1] = true;
            P.etype[P.n_emit] = 0; P.ew[P.n_emit] = w0; P.ew2[P.n_emit] = w1;
            P.n_emit++;
        } else {
            pk[w0][plen[w0]] = k; pkd[w0][plen[w0]] = kd; plen[w0]++;
        }
    }
    // Final per-wire U = trailing pendings + RX(theta_rx) + RY(theta_ry)
    for (int w = 0; w < 8; w++) {
        int m = P.n_mat++;
        int L = 0;
        for (int i = 0; i < plen[w]; i++) {
            P.mk[m][L] = pk[w][i]; P.mkind[m][L] = pkd[w][i]; L++;
        }
        P.mk[m][L] = -1; P.mkind[m][L] = 0; L++;
        P.mk[m][L] = -2; P.mkind[m][L] = 1; L++;
        P.mlen[m] = L;
        P.etype[P.n_emit] = 1; P.ew[P.n_emit] = w; P.ew2[P.n_emit] = m;
        P.n_emit++;
    }
    return P;
}

constexpr Plan PLAN = build_plan();
__constant__ Plan d_PLAN = build_plan();
constexpr int NMAT  = PLAN.n_mat;
constexpr int NEMIT = PLAN.n_emit;

constexpr int first_cplx(int lo, int hi) {
    for (int w = lo; w < hi; w++) if (PLAN.pre_len[w] > 0) return w;
    return -1;
}
constexpr int FT = first_cplx(0, 4);
constexpr int FJ = first_cplx(4, 8);

// ===========================================================================
// Packed f32x2 primitives. Amplitude = u64 packed (re = lo, im = hi).
// ===========================================================================
__device__ __forceinline__ u64 pk2(float lo, float hi) {
    u64 r; asm("mov.b64 %0, {%1, %2};" : "=l"(r) : "f"(lo), "f"(hi)); return r;
}
__device__ __forceinline__ void upk2(u64 v, float& lo, float& hi) {
    asm("mov.b64 {%0, %1}, %2;" : "=f"(lo), "=f"(hi) : "l"(v));
}
__device__ __forceinline__ u64 sw2(u64 v) {
    u64 r;
    asm("{\n\t.reg .b32 a, b;\n\tmov.b64 {a, b}, %1;\n\tmov.b64 %0, {b, a};\n\t}"
        : "=l"(r) : "l"(v));
    return r;
}
__device__ __forceinline__ u64 fma2(u64 a, u64 b, u64 c) {
    u64 d; asm("fma.rn.f32x2 %0, %1, %2, %3;" : "=l"(d) : "l"(a), "l"(b), "l"(c)); return d;
}
__device__ __forceinline__ u64 mul2(u64 a, u64 b) {
    u64 d; asm("mul.rn.f32x2 %0, %1, %2;" : "=l"(d) : "l"(a), "l"(b)); return d;
}
__device__ __forceinline__ u64 cmul(u64 p, u64 q) {   // complex multiply
    float pr, pi_; upk2(p, pr, pi_);
    return fma2(pk2(-pi_, pi_), sw2(q), mul2(pk2(pr, pr), q));
}
__device__ __forceinline__ u64 shfl_pk(u64 v, int m) {
    float lo, hi; upk2(v, lo, hi);
    float plo = __shfl_xor_sync(FULL, lo, m);
    float phi = __shfl_xor_sync(FULL, hi, m);
    return pk2(plo, phi);
}
__device__ __forceinline__ u64 shfl_pk_sw(u64 v, int m) {
    float lo, hi; upk2(v, lo, hi);
    float plo = __shfl_xor_sync(FULL, lo, m);
    float phi = __shfl_xor_sync(FULL, hi, m);
    return pk2(phi, plo);
}
__device__ __forceinline__ void shfl_pk_both(u64 v, int m, u64& q, u64& qsw) {
    float lo, hi; upk2(v, lo, hi);
    float plo = __shfl_xor_sync(FULL, lo, m);
    float phi = __shfl_xor_sync(FULL, hi, m);
    q = pk2(plo, phi); qsw = pk2(phi, plo);
}

// ===========================================================================
// Layout: 2 items per warp, 16 lanes per item (group bit = lane bit 4).
// Amplitude index bits: [7:4] = sublane t (lane bits 3..0), [3:0] = local j.
// Wire w <-> bit (7-w). BIT>=4: lane gate.
// ===========================================================================

template<int BIT>
__device__ __forceinline__ void rx_g(u64 (&v)[16], u64 CC, u64 SPN, int lane) {
    if constexpr (BIT >= 4) {
        constexpr int m = 1 << (BIT - 4);
#pragma unroll
        for (int j = 0; j < 16; j++) {
            u64 psw = shfl_pk_sw(v[j], m);
            v[j] = fma2(SPN, psw, mul2(CC, v[j]));
        }
    } else {
        constexpr int m = 1 << BIT;
#pragma unroll
        for (int j0 = 0; j0 < 16; j0++) {
            if ((j0 & m) == 0) {
                const int j1 = j0 | m;
                u64 sw0 = sw2(v[j0]), sw1 = sw2(v[j1]);
                v[j0] = fma2(SPN, sw1, mul2(CC, v[j0]));
                v[j1] = fma2(SPN, sw0, mul2(CC, v[j1]));
            }
        }
    }
}

template<int BIT>
__device__ __forceinline__ void ry_g(u64 (&v)[16], u64 CC, u64 SS, u64 SN, int lane) {
    if constexpr (BIT >= 4) {
        constexpr int m = 1 << (BIT - 4);
        u64 ssP = ((lane >> (BIT - 4)) & 1) ? SS : SN;
#pragma unroll
        for (int j = 0; j < 16; j++) {
            u64 p = shfl_pk(v[j], m);
            v[j] = fma2(ssP, p, mul2(CC, v[j]));
        }
    } else {
        constexpr int m = 1 << BIT;
#pragma unroll
        for (int j0 = 0; j0 < 16; j0++) {
            if ((j0 & m) == 0) {
                const int j1 = j0 | m;
                u64 v0 = v[j0], v1 = v[j1];
                v[j0] = fma2(SN, v1, mul2(CC, v0));
                v[j1] = fma2(SS, v0, mul2(CC, v1));
            }
        }
    }
}

template<int BIT>
__device__ __forceinline__ void rz_g(u64 (&v)[16], u64 CC, u64 SPN, u64 NSP, int lane) {
    if constexpr (BIT >= 4) {
        u64 zc = ((lane >> (BIT - 4)) & 1) ? NSP : SPN;
#pragma unroll
        for (int j = 0; j < 16; j++)
            v[j] = fma2(zc, sw2(v[j]), mul2(CC, v[j]));
    } else {
        constexpr int m = 1 << BIT;
#pragma unroll
        for (int j = 0; j < 16; j++) {
            u64 zc = (j & m) ? NSP : SPN;
            v[j] = fma2(zc, sw2(v[j]), mul2(CC, v[j]));
        }
    }
}

template<int CB, int TB>
__device__ __forceinline__ void cnot_g(u64 (&v)[16], int lane) {
    if constexpr (CB >= 4 && TB >= 4) {
        constexpr int mt = 1 << (TB - 4);
        bool ctl = (lane >> (CB - 4)) & 1;
#pragma unroll
        for (int j = 0; j < 16; j++) {
            u64 q = shfl_pk(v[j], mt);
            if (ctl) v[j] = q;
        }
    } else if constexpr (CB >= 4 && TB < 4) {
        constexpr int mt = 1 << TB;
        bool ctl = (lane >> (CB - 4)) & 1;
#pragma unroll
        for (int j0 = 0; j0 < 16; j0++) {
            if ((j0 & mt) == 0) {
                const int j1 = j0 | mt;
                u64 a = v[j0], b = v[j1];
                v[j0] = ctl ? b : a;
                v[j1] = ctl ? a : b;
            }
        }
    } else if constexpr (CB < 4 && TB >= 4) {
        constexpr int mc = 1 << CB;
        constexpr int mt = 1 << (TB - 4);
#pragma unroll
        for (int j = 0; j < 16; j++) {
            if (j & mc)
                v[j] = shfl_pk(v[j], mt);
        }
    } else {
        constexpr int mc = 1 << CB;
        constexpr int mt = 1 << TB;
#pragma unroll
        for (int j0 = 0; j0 < 16; j0++) {
            if ((j0 & mc) && !(j0 & mt)) {
                const int j1 = j0 | mt;
                u64 t = v[j0]; v[j0] = v[j1]; v[j1] = t;
            }
        }
    }
}

// General SU(2) gate U = [[ar+i*ai, br+i*bi], [-br+i*bi, ar-i*ai]]
template<int BIT>
__device__ __forceinline__ void u_g(u64 (&v)[16],
                                    u64 AR2, u64 AIP, u64 AIN,
                                    u64 BR2, u64 BRN2, u64 BIP, int lane) {
    if constexpr (BIT >= 4) {
        constexpr int m = 1 << (BIT - 4);
        bool hi = (lane >> (BIT - 4)) & 1;
        u64 DIP = hi ? AIN : AIP;
        u64 OR2 = hi ? BRN2 : BR2;
#pragma unroll
        for (int j = 0; j < 16; j++) {
            u64 q, qsw;
            shfl_pk_both(v[j], m, q, qsw);
            u64 vsw = sw2(v[j]);
            v[j] = fma2(AR2, v[j], fma2(DIP, vsw, fma2(OR2, q, mul2(BIP, qsw))));
        }
    } else {
        constexpr int m = 1 << BIT;
#pragma unroll
        for (int j0 = 0; j0 < 16; j0++) {
            if ((j0 & m) == 0) {
                const int j1 = j0 | m;
                u64 v0 = v[j0], v1 = v[j1];
                u64 sw0 = sw2(v0), sw1 = sw2(v1);
                v[j0] = fma2(AR2, v0, fma2(AIP, sw0, fma2(BR2,  v1, mul2(BIP, sw1))));
                v[j1] = fma2(BRN2, v0, fma2(BIP, sw0, fma2(AR2, v1, mul2(AIN, sw1))));
            }
        }
    }
}

// ---- Plan-driven emission ----
template<int E>
__device__ __forceinline__ void run_emit(u64 (&v)[16], const u64* __restrict__ s_rot,
                                         const u64* __restrict__ s_mats, int lane) {
    if constexpr (E < NEMIT) {
        constexpr int ty = PLAN.etype[E];
        if constexpr (ty == 0) {
            cnot_g<7 - PLAN.ew[E], 7 - PLAN.ew2[E]>(v, lane);
        } else if constexpr (ty == 1) {
            constexpr int m = PLAN.ew2[E];
            const u64* g = s_mats + m * 6;
            u_g<7 - PLAN.ew[E]>(v, g[0], g[1], g[2], g[3], g[4], g[5], lane);
        } else {
            constexpr int k = PLAN.ew2[E];
            constexpr int kd = PLAN.ekind[E];
            const u64* g = s_rot + k * 5;
            constexpr int bit = 7 - PLAN.ew[E];
            if constexpr (kd == 0)      rx_g<bit>(v, g[0], g[3], lane);
            else if constexpr (kd == 1) ry_g<bit>(v, g[0], g[1], g[2], lane);
            else                        rz_g<bit>(v, g[0], g[3], g[4], lane);
        }
        run_emit<E + 1>(v, s_rot, s_mats, lane);
    }
}

// ---- SU(2) composition (preamble): acc' = R * acc ----
__device__ void compose_su2(const int* ks, const int* kds, int len,
                            const float* __restrict__ rl, float tx, float ty,
                            float& ar, float& ai, float& br, float& bi) {
    ar = 1.f; ai = 0.f; br = 0.f; bi = 0.f;
    for (int i = 0; i < len; i++) {
        int k = ks[i], kd = kds[i];
        float ang = (k >= 0) ? rl[k] * 0.5f : ((k == -1) ? tx * 0.5f : ty * 0.5f);
        float c, s; sincosf(ang, &s, &c);
        float xr, xi, yr, yi;   // rotation (a_r, b_r)
        if (kd == 0)      { xr = c; xi = 0.f; yr = 0.f; yi = -s; }  // RX
        else if (kd == 1) { xr = c; xi = 0.f; yr = -s;  yi = 0.f; } // RY
        else              { xr = c; xi = -s;  yr = 0.f; yi = 0.f; } // RZ
        // new_a = x*a - y*conj(b) ; new_b = x*b + y*conj(a)
        float na_r = xr * ar - xi * ai - (yr * br + yi * bi);
        float na_i = xr * ai + xi * ar - (yi * br - yr * bi);
        float nb_r = xr * br - xi * bi + (yr * ar + yi * ai);
        float nb_i = xr * bi + xi * br + (yi * ar - yr * ai);
        ar = na_r; ai = na_i; br = nb_r; bi = nb_i;
    }
}

// ---- Init product accumulation (compile-time real/complex split) ----
template<int W>
__device__ __forceinline__ void gammas(u64 (&g0)[8], u64 (&g1)[8],
                                       const float* cw, const float* sw,
                                       const u64* __restrict__ s_pre) {
    if constexpr (W < 8) {
        if constexpr (PLAN.pre_len[W] > 0) {
            const u64* pp = s_pre + W * 4;   // A=(ar,ai) NA=(ar,-ai) B=(br,bi) NB=(-br,bi)
            u64 C2 = pk2(cw[W], cw[W]), S2 = pk2(sw[W], sw[W]);
            g0[W] = fma2(S2, pp[2], mul2(C2, pp[0]));   // gamma0 = a*c + b*s
            g1[W] = fma2(S2, pp[1], mul2(C2, pp[3]));   // gamma1 = -b**c + a**s
        }
        gammas<W + 1>(g0, g1, cw, sw, s_pre);
    }
}

template<int W>
__device__ __forceinline__ void t_accum(float& R, u64& C, int t,
                                        const float* cw, const float* sw,
                                        const u64 (&g0)[8], const u64 (&g1)[8]) {
    if constexpr (W < 4) {
        if constexpr (PLAN.pre_len[W] > 0) {
            u64 g = ((t >> (3 - W)) & 1) ? g1[W] : g0[W];
            if constexpr (W == FT) C = g; else C = cmul(C, g);
        } else {
            R *= ((t >> (3 - W)) & 1) ? sw[W] : cw[W];
        }
        t_accum<W + 1>(R, C, t, cw, sw, g0, g1);
    }
}

template<int W>
__device__ __forceinline__ void j_accum(float& R, u64& C, int j,
                                        const float* cw, const float* sw,
                                        const u64 (&g0)[8], const u64 (&g1)[8]) {
    if constexpr (W < 8) {
        if constexpr (PLAN.pre_len[W] > 0) {
            u64 g = ((j >> (7 - W)) & 1) ? g1[W] : g0[W];
            if constexpr (W == FJ) C = g; else C = cmul(C, g);
        } else {
            R *= ((j >> (7 - W)) & 1) ? sw[W] : cw[W];
        }
        j_accum<W + 1>(R, C, j, cw, sw, g0, g1);
    }
}

// ===========================================================================
// Main kernel: one warp per TWO batch items, 16 packed amps per lane.
// ===========================================================================
__global__ __launch_bounds__(256)
void qcnn_kernel(const float* __restrict__ x,
                 const float* __restrict__ rl,
                 const float* __restrict__ trx,
                 const float* __restrict__ tryy,
                 float* __restrict__ out, int bsz) {
    __shared__ u64 s_rot[N_OPS_C * 5];
    __shared__ u64 s_mats[NMAT * 6];
    __shared__ u64 s_pre[8 * 4];

    int tid = threadIdx.x;
    if (tid < N_OPS_C) {
        float c, s;
        sincosf(rl[tid] * 0.5f, &s, &c);
        u64* g = s_rot + tid * 5;
        g[0] = pk2(c, c);  g[1] = pk2(s, s);   g[2] = pk2(-s, -s);
        g[3] = pk2(s, -s); g[4] = pk2(-s, s);
    } else if (tid >= 32 && tid < 32 + NMAT) {
        int m = tid - 32;
        float ar, ai, br, bi;
        compose_su2(d_PLAN.mk[m], d_PLAN.mkind[m], d_PLAN.mlen[m],
                    rl, trx[0], tryy[0], ar, ai, br, bi);
        u64* g = s_mats + m * 6;
        g[0] = pk2(ar, ar);   g[1] = pk2(-ai, ai);  g[2] = pk2(ai, -ai);
        g[3] = pk2(br, br);   g[4] = pk2(-br, -br); g[5] = pk2(-bi, bi);
    } else if (tid >= 96 && tid < 104) {
        int w = tid - 96;
        if (d_PLAN.pre_len[w] > 0) {
            float ar, ai, br, bi;
            compose_su2(d_PLAN.pre_k[w], d_PLAN.pre_kind[w], d_PLAN.pre_len[w],
                        rl, trx[0], tryy[0], ar, ai, br, bi);
            u64* g = s_pre + w * 4;
            g[0] = pk2(ar, ai); g[1] = pk2(ar, -ai);
            g[2] = pk2(br, bi); g[3] = pk2(-br, bi);
        }
    }
    __syncthreads();

    int warp = blockIdx.x * (blockDim.x >> 5) + (tid >> 5);
    int lane = tid & 31;
    int t = lane & 15;
    long b = (long)warp * 2 + (lane >> 4);
    if (b >= bsz) return;

    // ---- Init: product state, with pre-CNOT rotations absorbed per wire ----
    float myc, mys;
    float ang = (t < 8) ? __ldg(x + b * 8 + t) * 0.5f : 0.0f;
    sincosf(ang, &mys, &myc);
    float cw[8], sw[8];
#pragma unroll
    for (int w = 0; w < 8; w++) {
        int src = (lane & 16) | w;
        cw[w] = __shfl_sync(FULL, myc, src);
        sw[w] = __shfl_sync(FULL, mys, src);
    }
    u64 g0[8], g1[8];
    gammas<0>(g0, g1, cw, sw, s_pre);

    float Rt = 1.0f; u64 Ct = 0;
    t_accum<0>(Rt, Ct, t, cw, sw, g0, g1);

    u64 v[16];
#pragma unroll
    for (int j = 0; j < 16; j++) {
        float R = Rt; u64 Cj = 0;
        j_accum<4>(R, Cj, j, cw, sw, g0, g1);
        if constexpr (FT >= 0 && FJ >= 0) v[j] = mul2(pk2(R, R), cmul(Ct, Cj));
        else if constexpr (FT >= 0)       v[j] = mul2(pk2(R, R), Ct);
        else if constexpr (FJ >= 0)       v[j] = mul2(pk2(R, R), Cj);
        else                              v[j] = pk2(R, 0.0f);
    }

    // ---- Fused circuit (CNOTs + fused/singleton gates + final U layer) ----
    run_emit<0>(v, s_rot, s_mats, lane);

    // ---- Readout ----
    float S = 0.f, A0 = 0.f, A1 = 0.f, A2 = 0.f, A3 = 0.f;
#pragma unroll
    for (int j = 0; j < 16; j++) {
        float r, i; upk2(v[j], r, i);
        float pj = fmaf(r, r, i * i);
        S  += pj;
        A0 += (j & 1)        ? -pj : pj;
        A1 += ((j >> 1) & 1) ? -pj : pj;
        A2 += ((j >> 2) & 1) ? -pj : pj;
        A3 += ((j >> 3) & 1) ? -pj : pj;
    }
#pragma unroll
    for (int off = 8; off; off >>= 1) {
        float pS = __shfl_xor_sync(FULL, S,  off);
        float p0 = __shfl_xor_sync(FULL, A0, off);
        float p1 = __shfl_xor_sync(FULL, A1, off);
        float p2 = __shfl_xor_sync(FULL, A2, off);
        float p3 = __shfl_xor_sync(FULL, A3, off);
        S  = (lane & off) ? (pS - S) : (S + pS);
        A0 += p0; A1 += p1; A2 += p2; A3 += p3;
    }
    float* o = out + (size_t)b * 8;
    if (t && !(t & (t - 1)))
        o[4 - __ffs(t)] = S;
    if (t == 0) {
        o[4] = A3; o[5] = A2; o[6] = A1; o[7] = A0;
    }
}

extern "C" void kernel_launch(void* const* d_in, const int* in_sizes, int n_in,
                              void* d_out, int out_size) {
    const float* x    = (const float*)d_in[0];
    const float* rl   = (const float*)d_in[1];
    const float* trx  = (const float*)d_in[2];
    const float* tryy = (const float*)d_in[3];
    float* out = (float*)d_out;

    int bsz = in_sizes[0] / N_QUBITS_C;

    int warps_per_block = 8;
    int items_per_block = warps_per_block * 2;
    dim3 block(warps_per_block * 32);
    dim3 grid((bsz + items_per_block - 1) / items_per_block);
    qcnn_kernel<<<grid, block>>>(x, rl, trx, tryy, out, bsz);
}

// round 7
// speedup vs baseline: 2.9487x; 1.0052x over previous
#include <cuda_runtime.h>
#include <cstdint>

#define FULL 0xffffffffu
#define N_OPS_C 20
#define N_QUBITS_C 8

using u64 = unsigned long long;

// ===========================================================================
// Compile-time reproduction of np.random.RandomState(0) draws for _RL_OPS
// (validated across R1/R3/R4/R5/R6: rel_err ~2e-7).
// ===========================================================================
struct OpsArr { int op[N_OPS_C]; };  // kind | (w0<<2) | (w1<<5); 0=rx 1=ry 2=rz 3=cnot

struct CxRng {
    uint32_t mt[624]; int mti;
    constexpr CxRng() : mt{}, mti(624) {
        mt[0] = 0u;
        for (int i = 1; i < 624; i++)
            mt[i] = 1812433253u * (mt[i - 1] ^ (mt[i - 1] >> 30)) + (uint32_t)i;
    }
    constexpr uint32_t next() {
        if (mti >= 624) {
            for (int i = 0; i < 624; i++) {
                uint32_t y = (mt[i] & 0x80000000u) | (mt[(i + 1) % 624] & 0x7fffffffu);
                mt[i] = mt[(i + 397) % 624] ^ (y >> 1) ^ ((y & 1u) ? 0x9908b0dfu : 0u);
            }
            mti = 0;
        }
        uint32_t y = mt[mti++];
        y ^= y >> 11;
        y ^= (y << 7) & 0x9d2c5680u;
        y ^= (y << 15) & 0xefc60000u;
        y ^= y >> 18;
        return y;
    }
    constexpr uint32_t interval(uint32_t mx) {
        if (mx == 0u) return 0u;
        uint32_t mask = mx;
        mask |= mask >> 1; mask |= mask >> 2; mask |= mask >> 4;
        mask |= mask >> 8; mask |= mask >> 16;
        uint32_t v = next() & mask;
        while (v > mx) v = next() & mask;
        return v;
    }
};

constexpr OpsArr build_ops_cx() {
    CxRng rng{};
    OpsArr ol{};
    for (int k = 0; k < N_OPS_C; k++) {
        int kd = (int)(rng.next() & 3u);
        int w0 = 0, w1 = 0;
        if (kd == 3) {
            int perm[8] = {0, 1, 2, 3, 4, 5, 6, 7};
            for (int i = 7; i > 0; i--) {
                uint32_t j = rng.interval((uint32_t)i);
                int t = perm[i]; perm[i] = perm[(int)j]; perm[(int)j] = t;
            }
            w0 = perm[0]; w1 = perm[1];
        } else {
            w0 = (int)(rng.next() & 7u);
        }
        ol.op[k] = kd | (w0 << 2) | (w1 << 5);
    }
    return ol;
}

constexpr OpsArr OPS = build_ops_cx();

// ===========================================================================
// Compile-time circuit compiler v2.
// Emission ops:
//   0 = plain CNOT           (ew=ctl, ew2=tgt)
//   1 = fused SU(2) U        (ew=wire, ew2=matrix idx)
//   2 = singleton rotation   (ew=wire, ew2=k, ekind=kind)
//   3 = CU = CNOT o U(tgt)   (ew=ctl, ew2=tgt, ekind=matrix idx)
// Commutation deferral: RZ slides across CNOT on its ctl wire; RX slides
// across CNOT on its tgt wire (suffix-deferred, merged into later gates /
// final layer). Pre-first-touch rotations absorbed into the init product.
// ===========================================================================
struct Plan {
    int n_emit;
    int etype[48], ew[48], ew2[48], ekind[48];
    int n_mat;
    int mlen[32], mk[32][24], mkind[32][24];
    int pre_len[8], pre_k[8][20], pre_kind[8][20];
};

constexpr Plan build_plan() {
    Plan P{};
    int plen[8] = {}; int pk[8][20] = {}; int pkd[8][20] = {};
    bool seen[8] = {};
    for (int k = 0; k < N_OPS_C; k++) {
        int o = OPS.op[k]; int kd = o & 3;
        int w0 = (o >> 2) & 7, w1 = (o >> 5) & 7;
        if (kd != 3) {
            pk[w0][plen[w0]] = k; pkd[w0][plen[w0]] = kd; plen[w0]++;
            continue;
        }
        int c = w0, t = w1;
        // --- ctl side: absorb (first touch) or flush non-RZ prefix ---
        if (!seen[c]) {
            P.pre_len[c] = plen[c];
            for (int i = 0; i < plen[c]; i++) {
                P.pre_k[c][i] = pk[c][i]; P.pre_kind[c][i] = pkd[c][i];
            }
            plen[c] = 0;
        } else {
            int split = plen[c];
            while (split > 0 && pkd[c][split - 1] == 2) split--;  // defer RZ suffix
            if (split == 1) {
                P.etype[P.n_emit] = 2; P.ew[P.n_emit] = c;
                P.ew2[P.n_emit] = pk[c][0]; P.ekind[P.n_emit] = pkd[c][0];
                P.n_emit++;
            } else if (split > 1) {
                int m = P.n_mat++;
                P.mlen[m] = split;
                for (int i = 0; i < split; i++) {
                    P.mk[m][i] = pk[c][i]; P.mkind[m][i] = pkd[c][i];
                }
                P.etype[P.n_emit] = 1; P.ew[P.n_emit] = c; P.ew2[P.n_emit] = m;
                P.n_emit++;
            }
            for (int i = split; i < plen[c]; i++) {
                pk[c][i - split] = pk[c][i]; pkd[c][i - split] = pkd[c][i];
            }
            plen[c] -= split;
        }
        seen[c] = true;
        // --- tgt side: absorb (first touch) or CU-fuse non-RX prefix ---
        bool cu = false;
        if (!seen[t]) {
            P.pre_len[t] = plen[t];
            for (int i = 0; i < plen[t]; i++) {
                P.pre_k[t][i] = pk[t][i]; P.pre_kind[t][i] = pkd[t][i];
            }
            plen[t] = 0;
        } else {
            int split = plen[t];
            while (split > 0 && pkd[t][split - 1] == 0) split--;  // defer RX suffix
            if (split > 0) {
                int m = P.n_mat++;
                P.mlen[m] = split;
                for (int i = 0; i < split; i++) {
                    P.mk[m][i] = pk[t][i]; P.mkind[m][i] = pkd[t][i];
                }
                P.etype[P.n_emit] = 3; P.ew[P.n_emit] = c; P.ew2[P.n_emit] = t;
                P.ekind[P.n_emit] = m; P.n_emit++;
                cu = true;
            }
            for (int i = split; i < plen[t]; i++) {
                pk[t][i - split] = pk[t][i]; pkd[t][i - split] = pkd[t][i];
            }
            plen[t] -= split;
        }
        seen[t] = true;
        if (!cu) {
            P.etype[P.n_emit] = 0; P.ew[P.n_emit] = c; P.ew2[P.n_emit] = t;
            P.n_emit++;
        }
    }
    // Final per-wire U = trailing pendings + RX(theta_rx) + RY(theta_ry)
    for (int w = 0; w < 8; w++) {
        int m = P.n_mat++;
        int L = 0;
        for (int i = 0; i < plen[w]; i++) {
            P.mk[m][L] = pk[w][i]; P.mkind[m][L] = pkd[w][i]; L++;
        }
        P.mk[m][L] = -1; P.mkind[m][L] = 0; L++;
        P.mk[m][L] = -2; P.mkind[m][L] = 1; L++;
        P.mlen[m] = L;
        P.etype[P.n_emit] = 1; P.ew[P.n_emit] = w; P.ew2[P.n_emit] = m;
        P.n_emit++;
    }
    return P;
}

constexpr Plan PLAN = build_plan();
__constant__ Plan d_PLAN = build_plan();
constexpr int NMAT  = PLAN.n_mat;
constexpr int NEMIT = PLAN.n_emit;

constexpr int first_cplx(int lo, int hi) {
    for (int w = lo; w < hi; w++) if (PLAN.pre_len[w] > 0) return w;
    return -1;
}
constexpr int FT = first_cplx(0, 4);
constexpr int FJ = first_cplx(4, 8);

// ===========================================================================
// Packed f32x2 primitives. Amplitude = u64 packed (re = lo, im = hi).
// ===========================================================================
__device__ __forceinline__ u64 pk2(float lo, float hi) {
    u64 r; asm("mov.b64 %0, {%1, %2};" : "=l"(r) : "f"(lo), "f"(hi)); return r;
}
__device__ __forceinline__ void upk2(u64 v, float& lo, float& hi) {
    asm("mov.b64 {%0, %1}, %2;" : "=f"(lo), "=f"(hi) : "l"(v));
}
__device__ __forceinline__ u64 sw2(u64 v) {
    u64 r;
    asm("{\n\t.reg .b32 a, b;\n\tmov.b64 {a, b}, %1;\n\tmov.b64 %0, {b, a};\n\t}"
        : "=l"(r) : "l"(v));
    return r;
}
__device__ __forceinline__ u64 fma2(u64 a, u64 b, u64 c) {
    u64 d; asm("fma.rn.f32x2 %0, %1, %2, %3;" : "=l"(d) : "l"(a), "l"(b), "l"(c)); return d;
}
__device__ __forceinline__ u64 mul2(u64 a, u64 b) {
    u64 d; asm("mul.rn.f32x2 %0, %1, %2;" : "=l"(d) : "l"(a), "l"(b)); return d;
}
__device__ __forceinline__ u64 cmul(u64 p, u64 q) {   // complex multiply
    float pr, pi_; upk2(p, pr, pi_);
    return fma2(pk2(-pi_, pi_), sw2(q), mul2(pk2(pr, pr), q));
}
__device__ __forceinline__ u64 shfl_pk(u64 v, int m) {
    float lo, hi; upk2(v, lo, hi);
    float plo = __shfl_xor_sync(FULL, lo, m);
    float phi = __shfl_xor_sync(FULL, hi, m);
    return pk2(plo, phi);
}
__device__ __forceinline__ u64 shfl_pk_sw(u64 v, int m) {
    float lo, hi; upk2(v, lo, hi);
    float plo = __shfl_xor_sync(FULL, lo, m);
    float phi = __shfl_xor_sync(FULL, hi, m);
    return pk2(phi, plo);
}
__device__ __forceinline__ void shfl_pk_both(u64 v, int m, u64& q, u64& qsw) {
    float lo, hi; upk2(v, lo, hi);
    float plo = __shfl_xor_sync(FULL, lo, m);
    float phi = __shfl_xor_sync(FULL, hi, m);
    q = pk2(plo, phi); qsw = pk2(phi, plo);
}

// ===========================================================================
// Layout: 2 items per warp, 16 lanes per item (group bit = lane bit 4).
// Amplitude index bits: [7:4] = sublane t (lane bits 3..0), [3:0] = local j.
// Wire w <-> bit (7-w). BIT>=4: lane gate.
// ===========================================================================

template<int BIT>
__device__ __forceinline__ void rx_g(u64 (&v)[16], u64 CC, u64 SPN, int lane) {
    if constexpr (BIT >= 4) {
        constexpr int m = 1 << (BIT - 4);
#pragma unroll
        for (int j = 0; j < 16; j++) {
            u64 psw = shfl_pk_sw(v[j], m);
            v[j] = fma2(SPN, psw, mul2(CC, v[j]));
        }
    } else {
        constexpr int m = 1 << BIT;
#pragma unroll
        for (int j0 = 0; j0 < 16; j0++) {
            if ((j0 & m) == 0) {
                const int j1 = j0 | m;
                u64 sw0 = sw2(v[j0]), sw1 = sw2(v[j1]);
                v[j0] = fma2(SPN, sw1, mul2(CC, v[j0]));
                v[j1] = fma2(SPN, sw0, mul2(CC, v[j1]));
            }
        }
    }
}

template<int BIT>
__device__ __forceinline__ void ry_g(u64 (&v)[16], u64 CC, u64 SS, u64 SN, int lane) {
    if constexpr (BIT >= 4) {
        constexpr int m = 1 << (BIT - 4);
        u64 ssP = ((lane >> (BIT - 4)) & 1) ? SS : SN;
#pragma unroll
        for (int j = 0; j < 16; j++) {
            u64 p = shfl_pk(v[j], m);
            v[j] = fma2(ssP, p, mul2(CC, v[j]));
        }
    } else {
        constexpr int m = 1 << BIT;
#pragma unroll
        for (int j0 = 0; j0 < 16; j0++) {
            if ((j0 & m) == 0) {
                const int j1 = j0 | m;
                u64 v0 = v[j0], v1 = v[j1];
                v[j0] = fma2(SN, v1, mul2(CC, v0));
                v[j1] = fma2(SS, v0, mul2(CC, v1));
            }
        }
    }
}

template<int BIT>
__device__ __forceinline__ void rz_g(u64 (&v)[16], u64 CC, u64 SPN, u64 NSP, int lane) {
    if constexpr (BIT >= 4) {
        u64 zc = ((lane >> (BIT - 4)) & 1) ? NSP : SPN;
#pragma unroll
        for (int j = 0; j < 16; j++)
            v[j] = fma2(zc, sw2(v[j]), mul2(CC, v[j]));
    } else {
        constexpr int m = 1 << BIT;
#pragma unroll
        for (int j = 0; j < 16; j++) {
            u64 zc = (j & m) ? NSP : SPN;
            v[j] = fma2(zc, sw2(v[j]), mul2(CC, v[j]));
        }
    }
}

template<int CB, int TB>
__device__ __forceinline__ void cnot_g(u64 (&v)[16], int lane) {
    if constexpr (CB >= 4 && TB >= 4) {
        constexpr int mt = 1 << (TB - 4);
        bool ctl = (lane >> (CB - 4)) & 1;
#pragma unroll
        for (int j = 0; j < 16; j++) {
            u64 q = shfl_pk(v[j], mt);
            if (ctl) v[j] = q;
        }
    } else if constexpr (CB >= 4 && TB < 4) {
        constexpr int mt = 1 << TB;
        bool ctl = (lane >> (CB - 4)) & 1;
#pragma unroll
        for (int j0 = 0; j0 < 16; j0++) {
            if ((j0 & mt) == 0) {
                const int j1 = j0 | mt;
                u64 a = v[j0], b = v[j1];
                v[j0] = ctl ? b : a;
                v[j1] = ctl ? a : b;
            }
        }
    } else if constexpr (CB < 4 && TB >= 4) {
        constexpr int mc = 1 << CB;
        constexpr int mt = 1 << (TB - 4);
#pragma unroll
        for (int j = 0; j < 16; j++) {
            if (j & mc)
                v[j] = shfl_pk(v[j], mt);
        }
    } else {
        constexpr int mc = 1 << CB;
        constexpr int mt = 1 << TB;
#pragma unroll
        for (int j0 = 0; j0 < 16; j0++) {
            if ((j0 & mc) && !(j0 & mt)) {
                const int j1 = j0 | mt;
                u64 t = v[j0]; v[j0] = v[j1]; v[j1] = t;
            }
        }
    }
}

// General SU(2) gate U = [[ar+i*ai, br+i*bi], [-br+i*bi, ar-i*ai]]
// packs g: [0]=AR2 (ar,ar) [1]=AIP (-ai,ai) [2]=AIN (ai,-ai)
//          [3]=BR2 (br,br) [4]=BRN2 (-br,-br) [5]=BIP (-bi,bi)
template<int BIT>
__device__ __forceinline__ void u_g(u64 (&v)[16],
                                    u64 AR2, u64 AIP, u64 AIN,
                                    u64 BR2, u64 BRN2, u64 BIP, int lane) {
    if constexpr (BIT >= 4) {
        constexpr int m = 1 << (BIT - 4);
        bool hi = (lane >> (BIT - 4)) & 1;
        u64 DIP = hi ? AIN : AIP;
        u64 OR2 = hi ? BRN2 : BR2;
#pragma unroll
        for (int j = 0; j < 16; j++) {
            u64 q, qsw;
            shfl_pk_both(v[j], m, q, qsw);
            u64 vsw = sw2(v[j]);
            v[j] = fma2(AR2, v[j], fma2(DIP, vsw, fma2(OR2, q, mul2(BIP, qsw))));
        }
    } else {
        constexpr int m = 1 << BIT;
#pragma unroll
        for (int j0 = 0; j0 < 16; j0++) {
            if ((j0 & m) == 0) {
                const int j1 = j0 | m;
                u64 v0 = v[j0], v1 = v[j1];
                u64 sw0 = sw2(v0), sw1 = sw2(v1);
                v[j0] = fma2(AR2, v0, fma2(AIP, sw0, fma2(BR2,  v1, mul2(BIP, sw1))));
                v[j1] = fma2(BRN2, v0, fma2(BIP, sw0, fma2(AR2, v1, mul2(AIN, sw1))));
            }
        }
    }
}

// CU = CNOT(ctl, tgt) o U(tgt): output row at (ctl, hi) is U's row (ctl? 1-hi : hi),
// with self/partner coefficient roles swapped when ctl=1. One pass, no CNOT pass.
template<int CB, int TB>
__device__ __forceinline__ void cu_g(u64 (&v)[16], const u64* __restrict__ g, int lane) {
    u64 AR2 = g[0], AIP = g[1], AIN = g[2], BR2 = g[3], BRN2 = g[4], BIP = g[5];
    if constexpr (TB >= 4) {
        constexpr int m = 1 << (TB - 4);
        bool hi = (lane >> (TB - 4)) & 1;
        if constexpr (CB >= 4) {
            bool ctl = (lane >> (CB - 4)) & 1;
            bool idx = ctl ? !hi : hi;
            u64 S1 = ctl ? (idx ? BRN2 : BR2) : AR2;
            u64 S2 = ctl ? BIP : (idx ? AIN : AIP);
            u64 T1 = ctl ? AR2 : (idx ? BRN2 : BR2);
            u64 T2 = ctl ? (idx ? AIN : AIP) : BIP;
#pragma unroll
            for (int j = 0; j < 16; j++) {
                u64 q, qsw;
                shfl_pk_both(v[j], m, q, qsw);
                u64 vsw = sw2(v[j]);
                v[j] = fma2(S1, v[j], fma2(S2, vsw, fma2(T1, q, mul2(T2, qsw))));
            }
        } else {
            constexpr int mc = 1 << CB;
            // ctl=0 packs (row hi, self=pA, partner=pB)
            u64 S1a = AR2,               S2a = hi ? AIN : AIP;
            u64 T1a = hi ? BRN2 : BR2,   T2a = BIP;
            // ctl=1 packs (row 1-hi, self=pB, partner=pA)
            u64 S1b = (!hi) ? BRN2 : BR2, S2b = BIP;
            u64 T1b = AR2,                T2b = (!hi) ? AIN : AIP;
#pragma unroll
            for (int j = 0; j < 16; j++) {
                u64 q, qsw;
                shfl_pk_both(v[j], m, q, qsw);
                u64 vsw = sw2(v[j]);
                if (j & mc)
                    v[j] = fma2(S1b, v[j], fma2(S2b, vsw, fma2(T1b, q, mul2(T2b, qsw))));
                else
                    v[j] = fma2(S1a, v[j], fma2(S2a, vsw, fma2(T1a, q, mul2(T2a, qsw))));
            }
        }
    } else {
        constexpr int m = 1 << TB;
        if constexpr (CB >= 4) {
            bool ctl = (lane >> (CB - 4)) & 1;
#pragma unroll
            for (int j0 = 0; j0 < 16; j0++) {
                if ((j0 & m) == 0) {
                    const int j1 = j0 | m;
                    u64 v0 = v[j0], v1 = v[j1];
                    u64 sw0 = sw2(v0), sw1 = sw2(v1);
                    u64 n0 = fma2(AR2, v0, fma2(AIP, sw0, fma2(BR2,  v1, mul2(BIP, sw1))));
                    u64 n1 = fma2(BRN2, v0, fma2(BIP, sw0, fma2(AR2, v1, mul2(AIN, sw1))));
                    v[j0] = ctl ? n1 : n0;
                    v[j1] = ctl ? n0 : n1;
                }
            }
        } else {
            constexpr int mc = 1 << CB;
#pragma unroll
            for (int j0 = 0; j0 < 16; j0++) {
                if ((j0 & m) == 0) {
                    const int j1 = j0 | m;
                    u64 v0 = v[j0], v1 = v[j1];
                    u64 sw0 = sw2(v0), sw1 = sw2(v1);
                    u64 n0 = fma2(AR2, v0, fma2(AIP, sw0, fma2(BR2,  v1, mul2(BIP, sw1))));
                    u64 n1 = fma2(BRN2, v0, fma2(BIP, sw0, fma2(AR2, v1, mul2(AIN, sw1))));
                    if (j0 & mc) { v[j0] = n1; v[j1] = n0; }
                    else         { v[j0] = n0; v[j1] = n1; }
                }
            }
        }
    }
}

// ---- Plan-driven emission ----
template<int E>
__device__ __forceinline__ void run_emit(u64 (&v)[16], const u64* __restrict__ s_rot,
                                         const u64* __restrict__ s_mats, int lane) {
    if constexpr (E < NEMIT) {
        constexpr int ty = PLAN.etype[E];
        if constexpr (ty == 0) {
            cnot_g<7 - PLAN.ew[E], 7 - PLAN.ew2[E]>(v, lane);
        } else if constexpr (ty == 1) {
            constexpr int m = PLAN.ew2[E];
            const u64* g = s_mats + m * 6;
            u_g<7 - PLAN.ew[E]>(v, g[0], g[1], g[2], g[3], g[4], g[5], lane);
        } else if constexpr (ty == 2) {
            constexpr int k = PLAN.ew2[E];
            constexpr int kd = PLAN.ekind[E];
            const u64* g = s_rot + k * 5;
            constexpr int bit = 7 - PLAN.ew[E];
            if constexpr (kd == 0)      rx_g<bit>(v, g[0], g[3], lane);
            else if constexpr (kd == 1) ry_g<bit>(v, g[0], g[1], g[2], lane);
            else                        rz_g<bit>(v, g[0], g[3], g[4], lane);
        } else {
            constexpr int m = PLAN.ekind[E];
            cu_g<7 - PLAN.ew[E], 7 - PLAN.ew2[E]>(v, s_mats + m * 6, lane);
        }
        run_emit<E + 1>(v, s_rot, s_mats, lane);
    }
}

// ---- SU(2) composition (preamble): acc' = R * acc ----
__device__ void compose_su2(const int* ks, const int* kds, int len,
                            const float* __restrict__ rl, float tx, float ty,
                            float& ar, float& ai, float& br, float& bi) {
    ar = 1.f; ai = 0.f; br = 0.f; bi = 0.f;
    for (int i = 0; i < len; i++) {
        int k = ks[i], kd = kds[i];
        float ang = (k >= 0) ? rl[k] * 0.5f : ((k == -1) ? tx * 0.5f : ty * 0.5f);
        float c, s; sincosf(ang, &s, &c);
        float xr, xi, yr, yi;
        if (kd == 0)      { xr = c; xi = 0.f; yr = 0.f; yi = -s; }  // RX
        else if (kd == 1) { xr = c; xi = 0.f; yr = -s;  yi = 0.f; } // RY
        else              { xr = c; xi = -s;  yr = 0.f; yi = 0.f; } // RZ
        float na_r = xr * ar - xi * ai - (yr * br + yi * bi);
        float na_i = xr * ai + xi * ar - (yi * br - yr * bi);
        float nb_r = xr * br - xi * bi + (yr * ar + yi * ai);
        float nb_i = xr * bi + xi * br + (yi * ar - yr * ai);
        ar = na_r; ai = na_i; br = nb_r; bi = nb_i;
    }
}

// ---- Init product accumulation (compile-time real/complex split) ----
template<int W>
__device__ __forceinline__ void gammas(u64 (&g0)[8], u64 (&g1)[8],
                                       const float* cw, const float* sw,
                                       const u64* __restrict__ s_pre) {
    if constexpr (W < 8) {
        if constexpr (PLAN.pre_len[W] > 0) {
            const u64* pp = s_pre + W * 4;
            u64 C2 = pk2(cw[W], cw[W]), S2 = pk2(sw[W], sw[W]);
            g0[W] = fma2(S2, pp[2], mul2(C2, pp[0]));
            g1[W] = fma2(S2, pp[1], mul2(C2, pp[3]));
        }
        gammas<W + 1>(g0, g1, cw, sw, s_pre);
    }
}

template<int W>
__device__ __forceinline__ void t_accum(float& R, u64& C, int t,
                                        const float* cw, const float* sw,
                                        const u64 (&g0)[8], const u64 (&g1)[8]) {
    if constexpr (W < 4) {
        if constexpr (PLAN.pre_len[W] > 0) {
            u64 g = ((t >> (3 - W)) & 1) ? g1[W] : g0[W];
            if constexpr (W == FT) C = g; else C = cmul(C, g);
        } else {
            R *= ((t >> (3 - W)) & 1) ? sw[W] : cw[W];
        }
        t_accum<W + 1>(R, C, t, cw, sw, g0, g1);
    }
}

template<int W>
__device__ __forceinline__ void j_accum(float& R, u64& C, int j,
                                        const float* cw, const float* sw,
                                        const u64 (&g0)[8], const u64 (&g1)[8]) {
    if constexpr (W < 8) {
        if constexpr (PLAN.pre_len[W] > 0) {
            u64 g = ((j >> (7 - W)) & 1) ? g1[W] : g0[W];
            if constexpr (W == FJ) C = g; else C = cmul(C, g);
        } else {
            R *= ((j >> (7 - W)) & 1) ? sw[W] : cw[W];
        }
        j_accum<W + 1>(R, C, j, cw, sw, g0, g1);
    }
}

// ===========================================================================
// Main kernel: one warp per TWO batch items, 16 packed amps per lane.
// ===========================================================================
__global__ __launch_bounds__(256)
void qcnn_kernel(const float* __restrict__ x,
                 const float* __restrict__ rl,
                 const float* __restrict__ trx,
                 const float* __restrict__ tryy,
                 float* __restrict__ out, int bsz) {
    __shared__ u64 s_rot[N_OPS_C * 5];
    __shared__ u64 s_mats[NMAT * 6];
    __shared__ u64 s_pre[8 * 4];

    int tid = threadIdx.x;
    if (tid < N_OPS_C) {
        float c, s;
        sincosf(rl[tid] * 0.5f, &s, &c);
        u64* g = s_rot + tid * 5;
        g[0] = pk2(c, c);  g[1] = pk2(s, s);   g[2] = pk2(-s, -s);
        g[3] = pk2(s, -s); g[4] = pk2(-s, s);
    } else if (tid >= 32 && tid < 32 + NMAT) {
        int m = tid - 32;
        float ar, ai, br, bi;
        compose_su2(d_PLAN.mk[m], d_PLAN.mkind[m], d_PLAN.mlen[m],
                    rl, trx[0], tryy[0], ar, ai, br, bi);
        u64* g = s_mats + m * 6;
        g[0] = pk2(ar, ar);   g[1] = pk2(-ai, ai);  g[2] = pk2(ai, -ai);
        g[3] = pk2(br, br);   g[4] = pk2(-br, -br); g[5] = pk2(-bi, bi);
    } else if (tid >= 96 && tid < 104) {
        int w = tid - 96;
        if (d_PLAN.pre_len[w] > 0) {
            float ar, ai, br, bi;
            compose_su2(d_PLAN.pre_k[w], d_PLAN.pre_kind[w], d_PLAN.pre_len[w],
                        rl, trx[0], tryy[0], ar, ai, br, bi);
            u64* g = s_pre + w * 4;
            g[0] = pk2(ar, ai); g[1] = pk2(ar, -ai);
            g[2] = pk2(br, bi); g[3] = pk2(-br, bi);
        }
    }
    __syncthreads();

    int warp = blockIdx.x * (blockDim.x >> 5) + (tid >> 5);
    int lane = tid & 31;
    int t = lane & 15;
    long b = (long)warp * 2 + (lane >> 4);
    if (b >= bsz) return;

    // ---- Init: product state with pre-touch rotations absorbed per wire ----
    float myc, mys;
    float ang = (t < 8) ? __ldg(x + b * 8 + t) * 0.5f : 0.0f;
    sincosf(ang, &mys, &myc);
    float cw[8], sw[8];
#pragma unroll
    for (int w = 0; w < 8; w++) {
        int src = (lane & 16) | w;
        cw[w] = __shfl_sync(FULL, myc, src);
        sw[w] = __shfl_sync(FULL, mys, src);
    }
    u64 g0[8], g1[8];
    gammas<0>(g0, g1, cw, sw, s_pre);

    float Rt = 1.0f; u64 Ct = 0;
    t_accum<0>(Rt, Ct, t, cw, sw, g0, g1);

    u64 v[16];
#pragma unroll
    for (int j = 0; j < 16; j++) {
        float R = Rt; u64 Cj = 0;
        j_accum<4>(R, Cj, j, cw, sw, g0, g1);
        if constexpr (FT >= 0 && FJ >= 0) v[j] = mul2(pk2(R, R), cmul(Ct, Cj));
        else if constexpr (FT >= 0)       v[j] = mul2(pk2(R, R), Ct);
        else if constexpr (FJ >= 0)       v[j] = mul2(pk2(R, R), Cj);
        else                              v[j] = pk2(R, 0.0f);
    }

    // ---- Compiled circuit (CU-fused CNOTs, deferred/fused gates, final U) ----
    run_emit<0>(v, s_rot, s_mats, lane);

    // ---- Readout ----
    float S = 0.f, A0 = 0.f, A1 = 0.f, A2 = 0.f, A3 = 0.f;
#pragma unroll
    for (int j = 0; j < 16; j++) {
        float r, i; upk2(v[j], r, i);
        float pj = fmaf(r, r, i * i);
        S  += pj;
        A0 += (j & 1)        ? -pj : pj;
        A1 += ((j >> 1) & 1) ? -pj : pj;
        A2 += ((j >> 2) & 1) ? -pj : pj;
        A3 += ((j >> 3) & 1) ? -pj : pj;
    }
#pragma unroll
    for (int off = 8; off; off >>= 1) {
        float pS = __shfl_xor_sync(FULL, S,  off);
        float p0 = __shfl_xor_sync(FULL, A0, off);
        float p1 = __shfl_xor_sync(FULL, A1, off);
        float p2 = __shfl_xor_sync(FULL, A2, off);
        float p3 = __shfl_xor_sync(FULL, A3, off);
        S  = (lane & off) ? (pS - S) : (S + pS);
        A0 += p0; A1 += p1; A2 += p2; A3 += p3;
    }
    float* o = out + (size_t)b * 8;
    if (t && !(t & (t - 1)))
        o[4 - __ffs(t)] = S;
    if (t == 0) {
        o[4] = A3; o[5] = A2; o[6] = A1; o[7] = A0;
    }
}

extern "C" void kernel_launch(void* const* d_in, const int* in_sizes, int n_in,
                              void* d_out, int out_size) {
    const float* x    = (const float*)d_in[0];
    const float* rl   = (const float*)d_in[1];
    const float* trx  = (const float*)d_in[2];
    const float* tryy = (const float*)d_in[3];
    float* out = (float*)d_out;

    int bsz = in_sizes[0] / N_QUBITS_C;

    int warps_per_block = 8;
    int items_per_block = warps_per_block * 2;
    dim3 block(warps_per_block * 32);
    dim3 grid((bsz + items_per_block - 1) / items_per_block);
    qcnn_kernel<<<grid, block>>>(x, rl, trx, tryy, out, bsz);
}

// round 11
// speedup vs baseline: 3.0625x; 1.0386x over previous
#include <cuda_runtime.h>
#include <cstdint>

#define FULL 0xffffffffu
#define N_OPS_C 20
#define N_QUBITS_C 8

using u64 = unsigned long long;

// ===========================================================================
// Compile-time reproduction of np.random.RandomState(0) draws for _RL_OPS
// (validated across R1/R3/R4/R5/R6/R7: rel_err ~2e-7..3.5e-7).
// ===========================================================================
struct OpsArr { int op[N_OPS_C]; };  // kind | (w0<<2) | (w1<<5); 0=rx 1=ry 2=rz 3=cnot

struct CxRng {
    uint32_t mt[624]; int mti;
    constexpr CxRng() : mt{}, mti(624) {
        mt[0] = 0u;
        for (int i = 1; i < 624; i++)
            mt[i] = 1812433253u * (mt[i - 1] ^ (mt[i - 1] >> 30)) + (uint32_t)i;
    }
    constexpr uint32_t next() {
        if (mti >= 624) {
            for (int i = 0; i < 624; i++) {
                uint32_t y = (mt[i] & 0x80000000u) | (mt[(i + 1) % 624] & 0x7fffffffu);
                mt[i] = mt[(i + 397) % 624] ^ (y >> 1) ^ ((y & 1u) ? 0x9908b0dfu : 0u);
            }
            mti = 0;
        }
        uint32_t y = mt[mti++];
        y ^= y >> 11;
        y ^= (y << 7) & 0x9d2c5680u;
        y ^= (y << 15) & 0xefc60000u;
        y ^= y >> 18;
        return y;
    }
    constexpr uint32_t interval(uint32_t mx) {
        if (mx == 0u) return 0u;
        uint32_t mask = mx;
        mask |= mask >> 1; mask |= mask >> 2; mask |= mask >> 4;
        mask |= mask >> 8; mask |= mask >> 16;
        uint32_t v = next() & mask;
        while (v > mx) v = next() & mask;
        return v;
    }
};

constexpr OpsArr build_ops_cx() {
    CxRng rng{};
    OpsArr ol{};
    for (int k = 0; k < N_OPS_C; k++) {
        int kd = (int)(rng.next() & 3u);
        int w0 = 0, w1 = 0;
        if (kd == 3) {
            int perm[8] = {0, 1, 2, 3, 4, 5, 6, 7};
            for (int i = 7; i > 0; i--) {
                uint32_t j = rng.interval((uint32_t)i);
                int t = perm[i]; perm[i] = perm[(int)j]; perm[(int)j] = t;
            }
            w0 = perm[0]; w1 = perm[1];
        } else {
            w0 = (int)(rng.next() & 7u);
        }
        ol.op[k] = kd | (w0 << 2) | (w1 << 5);
    }
    return ol;
}

constexpr OpsArr OPS = build_ops_cx();

// ===========================================================================
// Compile-time circuit compiler v3 = v2 (CU fusion + commutation deferral)
// + wire->bit permutation chosen to minimize shuffle passes.
// Emission ops:
//   0 = plain CNOT           (ew=ctl, ew2=tgt)
//   1 = fused SU(2) U        (ew=wire, ew2=matrix idx)
//   2 = singleton rotation   (ew=wire, ew2=k, ekind=kind)
//   3 = CU = CNOT o U(tgt)   (ew=ctl, ew2=tgt, ekind=matrix idx)
// ===========================================================================
struct Plan {
    int n_emit;
    int etype[48], ew[48], ew2[48], ekind[48];
    int n_mat;
    int mlen[32], mk[32][24], mkind[32][24];
    int pre_len[8], pre_k[8][20], pre_kind[8][20];
};

constexpr Plan build_plan() {
    Plan P{};
    int plen[8] = {}; int pk[8][20] = {}; int pkd[8][20] = {};
    bool seen[8] = {};
    for (int k = 0; k < N_OPS_C; k++) {
        int o = OPS.op[k]; int kd = o & 3;
        int w0 = (o >> 2) & 7, w1 = (o >> 5) & 7;
        if (kd != 3) {
            pk[w0][plen[w0]] = k; pkd[w0][plen[w0]] = kd; plen[w0]++;
            continue;
        }
        int c = w0, t = w1;
        // --- ctl side: absorb (first touch) or flush non-RZ prefix ---
        if (!seen[c]) {
            P.pre_len[c] = plen[c];
            for (int i = 0; i < plen[c]; i++) {
                P.pre_k[c][i] = pk[c][i]; P.pre_kind[c][i] = pkd[c][i];
            }
            plen[c] = 0;
        } else {
            int split = plen[c];
            while (split > 0 && pkd[c][split - 1] == 2) split--;  // defer RZ suffix
            if (split == 1) {
                P.etype[P.n_emit] = 2; P.ew[P.n_emit] = c;
                P.ew2[P.n_emit] = pk[c][0]; P.ekind[P.n_emit] = pkd[c][0];
                P.n_emit++;
            } else if (split > 1) {
                int m = P.n_mat++;
                P.mlen[m] = split;
                for (int i = 0; i < split; i++) {
                    P.mk[m][i] = pk[c][i]; P.mkind[m][i] = pkd[c][i];
                }
                P.etype[P.n_emit] = 1; P.ew[P.n_emit] = c; P.ew2[P.n_emit] = m;
                P.n_emit++;
            }
            for (int i = split; i < plen[c]; i++) {
                pk[c][i - split] = pk[c][i]; pkd[c][i - split] = pkd[c][i];
            }
            plen[c] -= split;
        }
        seen[c] = true;
        // --- tgt side: absorb (first touch) or CU-fuse non-RX prefix ---
        bool cu = false;
        if (!seen[t]) {
            P.pre_len[t] = plen[t];
            for (int i = 0; i < plen[t]; i++) {
                P.pre_k[t][i] = pk[t][i]; P.pre_kind[t][i] = pkd[t][i];
            }
            plen[t] = 0;
        } else {
            int split = plen[t];
            while (split > 0 && pkd[t][split - 1] == 0) split--;  // defer RX suffix
            if (split > 0) {
                int m = P.n_mat++;
                P.mlen[m] = split;
                for (int i = 0; i < split; i++) {
                    P.mk[m][i] = pk[t][i]; P.mkind[m][i] = pkd[t][i];
                }
                P.etype[P.n_emit] = 3; P.ew[P.n_emit] = c; P.ew2[P.n_emit] = t;
                P.ekind[P.n_emit] = m; P.n_emit++;
                cu = true;
            }
            for (int i = split; i < plen[t]; i++) {
                pk[t][i - split] = pk[t][i]; pkd[t][i - split] = pkd[t][i];
            }
            plen[t] -= split;
        }
        seen[t] = true;
        if (!cu) {
            P.etype[P.n_emit] = 0; P.ew[P.n_emit] = c; P.ew2[P.n_emit] = t;
            P.n_emit++;
        }
    }
    // Final per-wire U = trailing pendings + RX(theta_rx) + RY(theta_ry)
    for (int w = 0; w < 8; w++) {
        int m = P.n_mat++;
        int L = 0;
        for (int i = 0; i < plen[w]; i++) {
            P.mk[m][L] = pk[w][i]; P.mkind[m][L] = pkd[w][i]; L++;
        }
        P.mk[m][L] = -1; P.mkind[m][L] = 0; L++;
        P.mk[m][L] = -2; P.mkind[m][L] = 1; L++;
        P.mlen[m] = L;
        P.etype[P.n_emit] = 1; P.ew[P.n_emit] = w; P.ew2[P.n_emit] = m;
        P.n_emit++;
    }
    return P;
}

constexpr Plan PLAN = build_plan();
__constant__ Plan d_PLAN = build_plan();
constexpr int NMAT  = PLAN.n_mat;
constexpr int NEMIT = PLAN.n_emit;

// ---- Wire->bit permutation: minimize lane (shuffle-bearing) passes ----
// Shuffle cost per emitted op if wire is on a LANE bit:
//   U pass / RX / RY singleton on w   -> shuffles
//   CNOT or CU with target w          -> shuffles
//   RZ singleton on w                 -> free (diagonal)
//   CNOT/CU control on w              -> free (select only)
// Assign the 4 highest-weight wires to LOCAL bits (0..3), rest to LANE (4..7).
struct Perm { int wbit[8]; int wofb[8]; };

constexpr Perm build_perm() {
    int wgt[8] = {};
    for (int e = 0; e < PLAN.n_emit; e++) {
        int ty = PLAN.etype[e];
        if (ty == 0)      wgt[PLAN.ew2[e]]++;                        // CNOT tgt
        else if (ty == 1) wgt[PLAN.ew[e]]++;                         // U
        else if (ty == 2) { if (PLAN.ekind[e] != 2) wgt[PLAN.ew[e]]++; }  // non-RZ rot
        else              wgt[PLAN.ew2[e]]++;                        // CU tgt
    }
    Perm P{};
    int order[8] = {0, 1, 2, 3, 4, 5, 6, 7};
    for (int i = 0; i < 8; i++) {                 // selection sort, weight desc
        int best = i;
        for (int k = i + 1; k < 8; k++)
            if (wgt[order[k]] > wgt[order[best]]) best = k;
        int t = order[i]; order[i] = order[best]; order[best] = t;
    }
    for (int i = 0; i < 8; i++) { P.wbit[order[i]] = i; P.wofb[i] = order[i]; }
    return P;
}

constexpr Perm PERM = build_perm();
// Packed scalar copies for DEVICE-CODE runtime use (constexpr struct members
// can't be odr-used in device code; scalar constexpr ints fold to immediates).
constexpr int WOFB_HI = PERM.wofb[4] | (PERM.wofb[5] << 8)
                      | (PERM.wofb[6] << 16) | (PERM.wofb[7] << 24);
constexpr int WOFB_LO0 = PERM.wofb[0];
constexpr int WOFB_LO1 = PERM.wofb[1];
constexpr int WOFB_LO2 = PERM.wofb[2];
constexpr int WOFB_LO3 = PERM.wofb[3];

constexpr int first_lane_cplx() {
    for (int w = 0; w < 8; w++)
        if (PLAN.pre_len[w] > 0 && PERM.wbit[w] >= 4) return w;
    return -1;
}
constexpr int first_local_cplx() {
    for (int w = 0; w < 8; w++)
        if (PLAN.pre_len[w] > 0 && PERM.wbit[w] < 4) return w;
    return -1;
}
constexpr int FT = first_lane_cplx();
constexpr int FJ = first_local_cplx();

// ===========================================================================
// Packed f32x2 primitives. Amplitude = u64 packed (re = lo, im = hi).
// ===========================================================================
__device__ __forceinline__ u64 pk2(float lo, float hi) {
    u64 r; asm("mov.b64 %0, {%1, %2};" : "=l"(r) : "f"(lo), "f"(hi)); return r;
}
__device__ __forceinline__ void upk2(u64 v, float& lo, float& hi) {
    asm("mov.b64 {%0, %1}, %2;" : "=f"(lo), "=f"(hi) : "l"(v));
}
__device__ __forceinline__ u64 sw2(u64 v) {
    u64 r;
    asm("{\n\t.reg .b32 a, b;\n\tmov.b64 {a, b}, %1;\n\tmov.b64 %0, {b, a};\n\t}"
        : "=l"(r) : "l"(v));
    return r;
}
__device__ __forceinline__ u64 fma2(u64 a, u64 b, u64 c) {
    u64 d; asm("fma.rn.f32x2 %0, %1, %2, %3;" : "=l"(d) : "l"(a), "l"(b), "l"(c)); return d;
}
__device__ __forceinline__ u64 mul2(u64 a, u64 b) {
    u64 d; asm("mul.rn.f32x2 %0, %1, %2;" : "=l"(d) : "l"(a), "l"(b)); return d;
}
__device__ __forceinline__ u64 cmul(u64 p, u64 q) {
    float pr, pi_; upk2(p, pr, pi_);
    return fma2(pk2(-pi_, pi_), sw2(q), mul2(pk2(pr, pr), q));
}
__device__ __forceinline__ u64 shfl_pk(u64 v, int m) {
    float lo, hi; upk2(v, lo, hi);
    float plo = __shfl_xor_sync(FULL, lo, m);
    float phi = __shfl_xor_sync(FULL, hi, m);
    return pk2(plo, phi);
}
__device__ __forceinline__ u64 shfl_pk_sw(u64 v, int m) {
    float lo, hi; upk2(v, lo, hi);
    float plo = __shfl_xor_sync(FULL, lo, m);
    float phi = __shfl_xor_sync(FULL, hi, m);
    return pk2(phi, plo);
}
__device__ __forceinline__ void shfl_pk_both(u64 v, int m, u64& q, u64& qsw) {
    float lo, hi; upk2(v, lo, hi);
    float plo = __shfl_xor_sync(FULL, lo, m);
    float phi = __shfl_xor_sync(FULL, hi, m);
    q = pk2(plo, phi); qsw = pk2(phi, plo);
}

// ===========================================================================
// Layout: 2 items per warp, 16 lanes per item (group bit = lane bit 4).
// Amplitude index bits: [7:4] = sublane t (lane bits 3..0), [3:0] = local j.
// Wire w <-> bit PERM.wbit[w]. BIT>=4: lane gate; BIT<4: register-local.
// ===========================================================================

template<int BIT>
__device__ __forceinline__ void rx_g(u64 (&v)[16], u64 CC, u64 SPN, int lane) {
    if constexpr (BIT >= 4) {
        constexpr int m = 1 << (BIT - 4);
#pragma unroll
        for (int j = 0; j < 16; j++) {
            u64 psw = shfl_pk_sw(v[j], m);
            v[j] = fma2(SPN, psw, mul2(CC, v[j]));
        }
    } else {
        constexpr int m = 1 << BIT;
#pragma unroll
        for (int j0 = 0; j0 < 16; j0++) {
            if ((j0 & m) == 0) {
                const int j1 = j0 | m;
                u64 sw0 = sw2(v[j0]), sw1 = sw2(v[j1]);
                v[j0] = fma2(SPN, sw1, mul2(CC, v[j0]));
                v[j1] = fma2(SPN, sw0, mul2(CC, v[j1]));
            }
        }
    }
}

template<int BIT>
__device__ __forceinline__ void ry_g(u64 (&v)[16], u64 CC, u64 SS, u64 SN, int lane) {
    if constexpr (BIT >= 4) {
        constexpr int m = 1 << (BIT - 4);
        u64 ssP = ((lane >> (BIT - 4)) & 1) ? SS : SN;
#pragma unroll
        for (int j = 0; j < 16; j++) {
            u64 p = shfl_pk(v[j], m);
            v[j] = fma2(ssP, p, mul2(CC, v[j]));
        }
    } else {
        constexpr int m = 1 << BIT;
#pragma unroll
        for (int j0 = 0; j0 < 16; j0++) {
            if ((j0 & m) == 0) {
                const int j1 = j0 | m;
                u64 v0 = v[j0], v1 = v[j1];
                v[j0] = fma2(SN, v1, mul2(CC, v0));
                v[j1] = fma2(SS, v0, mul2(CC, v1));
            }
        }
    }
}

template<int BIT>
__device__ __forceinline__ void rz_g(u64 (&v)[16], u64 CC, u64 SPN, u64 NSP, int lane) {
    if constexpr (BIT >= 4) {
        u64 zc = ((lane >> (BIT - 4)) & 1) ? NSP : SPN;
#pragma unroll
        for (int j = 0; j < 16; j++)
            v[j] = fma2(zc, sw2(v[j]), mul2(CC, v[j]));
    } else {
        constexpr int m = 1 << BIT;
#pragma unroll
        for (int j = 0; j < 16; j++) {
            u64 zc = (j & m) ? NSP : SPN;
            v[j] = fma2(zc, sw2(v[j]), mul2(CC, v[j]));
        }
    }
}

template<int CB, int TB>
__device__ __forceinline__ void cnot_g(u64 (&v)[16], int lane) {
    if constexpr (CB >= 4 && TB >= 4) {
        constexpr int mt = 1 << (TB - 4);
        bool ctl = (lane >> (CB - 4)) & 1;
#pragma unroll
        for (int j = 0; j < 16; j++) {
            u64 q = shfl_pk(v[j], mt);
            if (ctl) v[j] = q;
        }
    } else if constexpr (CB >= 4 && TB < 4) {
        constexpr int mt = 1 << TB;
        bool ctl = (lane >> (CB - 4)) & 1;
#pragma unroll
        for (int j0 = 0; j0 < 16; j0++) {
            if ((j0 & mt) == 0) {
                const int j1 = j0 | mt;
                u64 a = v[j0], b = v[j1];
                v[j0] = ctl ? b : a;
                v[j1] = ctl ? a : b;
            }
        }
    } else if constexpr (CB < 4 && TB >= 4) {
        constexpr int mc = 1 << CB;
        constexpr int mt = 1 << (TB - 4);
#pragma unroll
        for (int j = 0; j < 16; j++) {
            if (j & mc)
                v[j] = shfl_pk(v[j], mt);
        }
    } else {
        constexpr int mc = 1 << CB;
        constexpr int mt = 1 << TB;
#pragma unroll
        for (int j0 = 0; j0 < 16; j0++) {
            if ((j0 & mc) && !(j0 & mt)) {
                const int j1 = j0 | mt;
                u64 t = v[j0]; v[j0] = v[j1]; v[j1] = t;
            }
        }
    }
}

// General SU(2) gate U = [[ar+i*ai, br+i*bi], [-br+i*bi, ar-i*ai]]
template<int BIT>
__device__ __forceinline__ void u_g(u64 (&v)[16],
                                    u64 AR2, u64 AIP, u64 AIN,
                                    u64 BR2, u64 BRN2, u64 BIP, int lane) {
    if constexpr (BIT >= 4) {
        constexpr int m = 1 << (BIT - 4);
        bool hi = (lane >> (BIT - 4)) & 1;
        u64 DIP = hi ? AIN : AIP;
        u64 OR2 = hi ? BRN2 : BR2;
#pragma unroll
        for (int j = 0; j < 16; j++) {
            u64 q, qsw;
            shfl_pk_both(v[j], m, q, qsw);
            u64 vsw = sw2(v[j]);
            v[j] = fma2(AR2, v[j], fma2(DIP, vsw, fma2(OR2, q, mul2(BIP, qsw))));
        }
    } else {
        constexpr int m = 1 << BIT;
#pragma unroll
        for (int j0 = 0; j0 < 16; j0++) {
            if ((j0 & m) == 0) {
                const int j1 = j0 | m;
                u64 v0 = v[j0], v1 = v[j1];
                u64 sw0 = sw2(v0), sw1 = sw2(v1);
                v[j0] = fma2(AR2, v0, fma2(AIP, sw0, fma2(BR2,  v1, mul2(BIP, sw1))));
                v[j1] = fma2(BRN2, v0, fma2(BIP, sw0, fma2(AR2, v1, mul2(AIN, sw1))));
            }
        }
    }
}

// CU = CNOT(ctl, tgt) o U(tgt)
template<int CB, int TB>
__device__ __forceinline__ void cu_g(u64 (&v)[16], const u64* __restrict__ g, int lane) {
    u64 AR2 = g[0], AIP = g[1], AIN = g[2], BR2 = g[3], BRN2 = g[4], BIP = g[5];
    if constexpr (TB >= 4) {
        constexpr int m = 1 << (TB - 4);
        bool hi = (lane >> (TB - 4)) & 1;
        if constexpr (CB >= 4) {
            bool ctl = (lane >> (CB - 4)) & 1;
            bool idx = ctl ? !hi : hi;
            u64 S1 = ctl ? (idx ? BRN2 : BR2) : AR2;
            u64 S2 = ctl ? BIP : (idx ? AIN : AIP);
            u64 T1 = ctl ? AR2 : (idx ? BRN2 : BR2);
            u64 T2 = ctl ? (idx ? AIN : AIP) : BIP;
#pragma unroll
            for (int j = 0; j < 16; j++) {
                u64 q, qsw;
                shfl_pk_both(v[j], m, q, qsw);
                u64 vsw = sw2(v[j]);
                v[j] = fma2(S1, v[j], fma2(S2, vsw, fma2(T1, q, mul2(T2, qsw))));
            }
        } else {
            constexpr int mc = 1 << CB;
            u64 S1a = AR2,               S2a = hi ? AIN : AIP;
            u64 T1a = hi ? BRN2 : BR2,   T2a = BIP;
            u64 S1b = (!hi) ? BRN2 : BR2, S2b = BIP;
            u64 T1b = AR2,                T2b = (!hi) ? AIN : AIP;
#pragma unroll
            for (int j = 0; j < 16; j++) {
                u64 q, qsw;
                shfl_pk_both(v[j], m, q, qsw);
                u64 vsw = sw2(v[j]);
                if (j & mc)
                    v[j] = fma2(S1b, v[j], fma2(S2b, vsw, fma2(T1b, q, mul2(T2b, qsw))));
                else
                    v[j] = fma2(S1a, v[j], fma2(S2a, vsw, fma2(T1a, q, mul2(T2a, qsw))));
            }
        }
    } else {
        constexpr int m = 1 << TB;
        if constexpr (CB >= 4) {
            bool ctl = (lane >> (CB - 4)) & 1;
#pragma unroll
            for (int j0 = 0; j0 < 16; j0++) {
                if ((j0 & m) == 0) {
                    const int j1 = j0 | m;
                    u64 v0 = v[j0], v1 = v[j1];
                    u64 sw0 = sw2(v0), sw1 = sw2(v1);
                    u64 n0 = fma2(AR2, v0, fma2(AIP, sw0, fma2(BR2,  v1, mul2(BIP, sw1))));
                    u64 n1 = fma2(BRN2, v0, fma2(BIP, sw0, fma2(AR2, v1, mul2(AIN, sw1))));
                    v[j0] = ctl ? n1 : n0;
                    v[j1] = ctl ? n0 : n1;
                }
            }
        } else {
            constexpr int mc = 1 << CB;
#pragma unroll
            for (int j0 = 0; j0 < 16; j0++) {
                if ((j0 & m) == 0) {
                    const int j1 = j0 | m;
                    u64 v0 = v[j0], v1 = v[j1];
                    u64 sw0 = sw2(v0), sw1 = sw2(v1);
                    u64 n0 = fma2(AR2, v0, fma2(AIP, sw0, fma2(BR2,  v1, mul2(BIP, sw1))));
                    u64 n1 = fma2(BRN2, v0, fma2(BIP, sw0, fma2(AR2, v1, mul2(AIN, sw1))));
                    if (j0 & mc) { v[j0] = n1; v[j1] = n0; }
                    else         { v[j0] = n0; v[j1] = n1; }
                }
            }
        }
    }
}

// ---- Plan-driven emission (bits via PERM, all as template args) ----
template<int E>
__device__ __forceinline__ void run_emit(u64 (&v)[16], const u64* __restrict__ s_rot,
                                         const u64* __restrict__ s_mats, int lane) {
    if constexpr (E < NEMIT) {
        constexpr int ty = PLAN.etype[E];
        if constexpr (ty == 0) {
            cnot_g<PERM.wbit[PLAN.ew[E]], PERM.wbit[PLAN.ew2[E]]>(v, lane);
        } else if constexpr (ty == 1) {
            constexpr int m = PLAN.ew2[E];
            const u64* g = s_mats + m * 6;
            u_g<PERM.wbit[PLAN.ew[E]]>(v, g[0], g[1], g[2], g[3], g[4], g[5], lane);
        } else if constexpr (ty == 2) {
            constexpr int k = PLAN.ew2[E];
            constexpr int kd = PLAN.ekind[E];
            const u64* g = s_rot + k * 5;
            constexpr int bit = PERM.wbit[PLAN.ew[E]];
            if constexpr (kd == 0)      rx_g<bit>(v, g[0], g[3], lane);
            else if constexpr (kd == 1) ry_g<bit>(v, g[0], g[1], g[2], lane);
            else                        rz_g<bit>(v, g[0], g[3], g[4], lane);
        } else {
            constexpr int m = PLAN.ekind[E];
            cu_g<PERM.wbit[PLAN.ew[E]], PERM.wbit[PLAN.ew2[E]]>(v, s_mats + m * 6, lane);
        }
        run_emit<E + 1>(v, s_rot, s_mats, lane);
    }
}

// ---- SU(2) composition (preamble): acc' = R * acc ----
__device__ void compose_su2(const int* ks, const int* kds, int len,
                            const float* __restrict__ rl, float tx, float ty,
                            float& ar, float& ai, float& br, float& bi) {
    ar = 1.f; ai = 0.f; br = 0.f; bi = 0.f;
    for (int i = 0; i < len; i++) {
        int k = ks[i], kd = kds[i];
        float ang = (k >= 0) ? rl[k] * 0.5f : ((k == -1) ? tx * 0.5f : ty * 0.5f);
        float c, s; sincosf(ang, &s, &c);
        float xr, xi, yr, yi;
        if (kd == 0)      { xr = c; xi = 0.f; yr = 0.f; yi = -s; }  // RX
        else if (kd == 1) { xr = c; xi = 0.f; yr = -s;  yi = 0.f; } // RY
        else              { xr = c; xi = -s;  yr = 0.f; yi = 0.f; } // RZ
        float na_r = xr * ar - xi * ai - (yr * br + yi * bi);
        float na_i = xr * ai + xi * ar - (yi * br - yr * bi);
        float nb_r = xr * br - xi * bi + (yr * ar + yi * ai);
        float nb_i = xr * bi + xi * br + (yi * ar - yr * ai);
        ar = na_r; ai = na_i; br = nb_r; bi = nb_i;
    }
}

// ---- Init product accumulation (wire->bit via PERM, compile-time only) ----
template<int W>
__device__ __forceinline__ void gammas(u64 (&g0)[8], u64 (&g1)[8],
                                       const float* cw, const float* sw,
                                       const u64* __restrict__ s_pre) {
    if constexpr (W < 8) {
        if constexpr (PLAN.pre_len[W] > 0) {
            const u64* pp = s_pre + W * 4;
            u64 C2 = pk2(cw[W], cw[W]), S2 = pk2(sw[W], sw[W]);
            g0[W] = fma2(S2, pp[2], mul2(C2, pp[0]));
            g1[W] = fma2(S2, pp[1], mul2(C2, pp[3]));
        }
        gammas<W + 1>(g0, g1, cw, sw, s_pre);
    }
}

template<int W>
__device__ __forceinline__ void t_accum(float& R, u64& C, int t,
                                        const float* cw, const float* sw,
                                        const u64 (&g0)[8], const u64 (&g1)[8]) {
    if constexpr (W < 8) {
        if constexpr (PERM.wbit[W] >= 4) {
            constexpr int tb = PERM.wbit[W] - 4;
            if constexpr (PLAN.pre_len[W] > 0) {
                u64 g = ((t >> tb) & 1) ? g1[W] : g0[W];
                if constexpr (W == FT) C = g; else C = cmul(C, g);
            } else {
                R *= ((t >> tb) & 1) ? sw[W] : cw[W];
            }
        }
        t_accum<W + 1>(R, C, t, cw, sw, g0, g1);
    }
}

template<int W>
__device__ __forceinline__ void j_accum(float& R, u64& C, int j,
                                        const float* cw, const float* sw,
                                        const u64 (&g0)[8], const u64 (&g1)[8]) {
    if constexpr (W < 8) {
        if constexpr (PERM.wbit[W] < 4) {
            constexpr int jb = PERM.wbit[W];
            if constexpr (PLAN.pre_len[W] > 0) {
                u64 g = ((j >> jb) & 1) ? g1[W] : g0[W];
                if constexpr (W == FJ) C = g; else C = cmul(C, g);
            } else {
                R *= ((j >> jb) & 1) ? sw[W] : cw[W];
            }
        }
        j_accum<W + 1>(R, C, j, cw, sw, g0, g1);
    }
}

// ===========================================================================
// Main kernel: one warp per TWO batch items, 16 packed amps per lane.
// ===========================================================================
__global__ __launch_bounds__(256)
void qcnn_kernel(const float* __restrict__ x,
                 const float* __restrict__ rl,
                 const float* __restrict__ trx,
                 const float* __restrict__ tryy,
                 float* __restrict__ out, int bsz) {
    __shared__ u64 s_rot[N_OPS_C * 5];
    __shared__ u64 s_mats[NMAT * 6];
    __shared__ u64 s_pre[8 * 4];

    int tid = threadIdx.x;
    if (tid < N_OPS_C) {
        float c, s;
        sincosf(rl[tid] * 0.5f, &s, &c);
        u64* g = s_rot + tid * 5;
        g[0] = pk2(c, c);  g[1] = pk2(s, s);   g[2] = pk2(-s, -s);
        g[3] = pk2(s, -s); g[4] = pk2(-s, s);
    } else if (tid >= 32 && tid < 32 + NMAT) {
        int m = tid - 32;
        float ar, ai, br, bi;
        compose_su2(d_PLAN.mk[m], d_PLAN.mkind[m], d_PLAN.mlen[m],
                    rl, trx[0], tryy[0], ar, ai, br, bi);
        u64* g = s_mats + m * 6;
        g[0] = pk2(ar, ar);   g[1] = pk2(-ai, ai);  g[2] = pk2(ai, -ai);
        g[3] = pk2(br, br);   g[4] = pk2(-br, -br); g[5] = pk2(-bi, bi);
    } else if (tid >= 96 && tid < 104) {
        int w = tid - 96;
        if (d_PLAN.pre_len[w] > 0) {
            float ar, ai, br, bi;
            compose_su2(d_PLAN.pre_k[w], d_PLAN.pre_kind[w], d_PLAN.pre_len[w],
                        rl, trx[0], tryy[0], ar, ai, br, bi);
            u64* g = s_pre + w * 4;
            g[0] = pk2(ar, ai); g[1] = pk2(ar, -ai);
            g[2] = pk2(br, bi); g[3] = pk2(-br, bi);
        }
    }
    __syncthreads();

    int warp = blockIdx.x * (blockDim.x >> 5) + (tid >> 5);
    int lane = tid & 31;
    int t = lane & 15;
    long b = (long)warp * 2 + (lane >> 4);
    if (b >= bsz) return;

    // ---- Init: product state with pre-touch rotations absorbed per wire ----
    float myc, mys;
    float ang = (t < 8) ? __ldg(x + b * 8 + t) * 0.5f : 0.0f;
    sincosf(ang, &mys, &myc);
    float cw[8], sw[8];
#pragma unroll
    for (int w = 0; w < 8; w++) {
        int src = (lane & 16) | w;
        cw[w] = __shfl_sync(FULL, myc, src);
        sw[w] = __shfl_sync(FULL, mys, src);
    }
    u64 g0[8], g1[8];
    gammas<0>(g0, g1, cw, sw, s_pre);

    float Rt = 1.0f; u64 Ct = 0;
    t_accum<0>(Rt, Ct, t, cw, sw, g0, g1);

    u64 v[16];
#pragma unroll
    for (int j = 0; j < 16; j++) {
        float R = Rt; u64 Cj = 0;
        j_accum<0>(R, Cj, j, cw, sw, g0, g1);
        if constexpr (FT >= 0 && FJ >= 0) v[j] = mul2(pk2(R, R), cmul(Ct, Cj));
        else if constexpr (FT >= 0)       v[j] = mul2(pk2(R, R), Ct);
        else if constexpr (FJ >= 0)       v[j] = mul2(pk2(R, R), Cj);
        else                              v[j] = pk2(R, 0.0f);
    }

    // ---- Compiled circuit ----
    run_emit<0>(v, s_rot, s_mats, lane);

    // ---- Readout ----
    // A_b = Z-sum partials for LOCAL bit b; S feeds the FWHT for lane bits.
    float S = 0.f, A0 = 0.f, A1 = 0.f, A2 = 0.f, A3 = 0.f;
#pragma unroll
    for (int j = 0; j < 16; j++) {
        float r, i; upk2(v[j], r, i);
        float pj = fmaf(r, r, i * i);
        S  += pj;
        A0 += (j & 1)        ? -pj : pj;
        A1 += ((j >> 1) & 1) ? -pj : pj;
        A2 += ((j >> 2) & 1) ? -pj : pj;
        A3 += ((j >> 3) & 1) ? -pj : pj;
    }
#pragma unroll
    for (int off = 8; off; off >>= 1) {
        float pS = __shfl_xor_sync(FULL, S,  off);
        float p0 = __shfl_xor_sync(FULL, A0, off);
        float p1 = __shfl_xor_sync(FULL, A1, off);
        float p2 = __shfl_xor_sync(FULL, A2, off);
        float p3 = __shfl_xor_sync(FULL, A3, off);
        S  = (lane & off) ? (pS - S) : (S + pS);
        A0 += p0; A1 += p1; A2 += p2; A3 += p3;
    }
    // Lane t=2^k holds ZS for lane bit k (global bit 4+k) -> wire WOFB_HI byte k.
    float* o = out + (size_t)b * 8;
    if (t && !(t & (t - 1))) {
        int k = __ffs(t) - 1;
        o[(WOFB_HI >> (8 * k)) & 0xff] = S;
    }
    if (t == 0) {
        o[WOFB_LO0] = A0; o[WOFB_LO1] = A1;
        o[WOFB_LO2] = A2; o[WOFB_LO3] = A3;
    }
}

extern "C" void kernel_launch(void* const* d_in, const int* in_sizes, int n_in,
                              void* d_out, int out_size) {
    const float* x    = (const float*)d_in[0];
    const float* rl   = (const float*)d_in[1];
    const float* trx  = (const float*)d_in[2];
    const float* tryy = (const float*)d_in[3];
    float* out = (float*)d_out;

    int bsz = in_sizes[0] / N_QUBITS_C;

    int warps_per_block = 8;
    int items_per_block = warps_per_block * 2;
    dim3 block(warps_per_block * 32);
    dim3 grid((bsz + items_per_block - 1) / items_per_block);
    qcnn_kernel<<<grid, block>>>(x, rl, trx, tryy, out, bsz);
}